// round 1
// baseline (speedup 1.0000x reference)
#include <cuda_runtime.h>
#include <cuda_bf16.h>
#include <cstdint>

#define NN 50000
#define EE 800000
#define DD 200
#define RR 500
#define LL 2

// ---------------- scratch (static device globals; no allocation) -------------
__device__ float g_h0[(size_t)NN * DD];
__device__ float g_h1[(size_t)NN * DD];
__device__ float g_agg[(size_t)NN * DD];
__device__ int   g_indeg[NN];
__device__ int   g_off[NN + 1];
__device__ int   g_cur[NN];
__device__ int   g_eid[EE];
__device__ int   g_list_in[NN];
__device__ int   g_list_no[NN];
__device__ int   g_cnt[2];   // [0]=count(indeg>0), [1]=count(indeg==0)

// ---------------- small setup kernels ---------------------------------------
__global__ void zero_k() {
    int i = blockIdx.x * blockDim.x + threadIdx.x;
    if (i < NN) g_indeg[i] = 0;
    if (i < 2)  g_cnt[i] = 0;
}

__global__ void count_k(const int* __restrict__ dst) {
    int e = blockIdx.x * blockDim.x + threadIdx.x;
    if (e < EE) atomicAdd(&g_indeg[dst[e]], 1);
}

// single-block exclusive scan over g_indeg -> g_off, also copies to g_cur
__global__ void scan_k() {
    __shared__ int sh[1024];
    __shared__ int carry;
    int tid = threadIdx.x;
    if (tid == 0) carry = 0;
    __syncthreads();
    for (int base = 0; base < NN; base += 1024) {
        int idx = base + tid;
        int v = (idx < NN) ? g_indeg[idx] : 0;
        sh[tid] = v;
        __syncthreads();
        for (int off = 1; off < 1024; off <<= 1) {
            int t = (tid >= off) ? sh[tid - off] : 0;
            __syncthreads();
            sh[tid] += t;
            __syncthreads();
        }
        int inc = sh[tid];
        int exc = inc - v;
        if (idx < NN) {
            int o = carry + exc;
            g_off[idx] = o;
            g_cur[idx] = o;
        }
        __syncthreads();
        if (tid == 1023) carry += sh[1023];
        __syncthreads();
    }
    if (tid == 0) g_off[NN] = carry;
}

__global__ void part_k() {
    int i = blockIdx.x * blockDim.x + threadIdx.x;
    if (i < NN) {
        if (g_indeg[i] > 0) {
            int p = atomicAdd(&g_cnt[0], 1);
            g_list_in[p] = i;
        } else {
            int p = atomicAdd(&g_cnt[1], 1);
            g_list_no[p] = i;
        }
    }
}

__global__ void fill_k(const int* __restrict__ dst) {
    int e = blockIdx.x * blockDim.x + threadIdx.x;
    if (e < EE) {
        int p = atomicAdd(&g_cur[dst[e]], 1);
        g_eid[p] = e;
    }
}

__global__ void init_k(const float* __restrict__ emb, const int* __restrict__ node_id) {
    long idx = (long)blockIdx.x * blockDim.x + threadIdx.x;
    if (idx >= (long)NN * DD) return;
    int i = (int)(idx / DD);
    int d = (int)(idx - (long)i * DD);
    g_h0[idx] = emb[(long)node_id[i] * DD + d];
}

// ---------------- per-layer: gather + segment sum, pre-scaled by norm -------
__global__ void agg_k(const float* __restrict__ h, const float* __restrict__ rel,
                      const int* __restrict__ src, const int* __restrict__ et,
                      const float* __restrict__ norm) {
    int i = blockIdx.x;
    int d = threadIdx.x;
    if (d >= DD) return;
    int s0 = g_off[i], s1 = g_off[i + 1];
    float acc = 0.f;
    for (int p = s0; p < s1; p++) {
        int e = g_eid[p];
        acc += h[(long)src[e] * DD + d] + rel[(long)et[e] * DD + d];
    }
    g_agg[(long)i * DD + d] = acc * norm[i];
}

// ---------------- fused GEMM: out = rrelu(agg@Wn + h@Wsel) over a row list --
// BM=128, BN=64, BK=8; 256 threads; 8x4 microtile per thread.
#define BM 128
#define BN 64
#define BK 8

__global__ __launch_bounds__(256) void gemm_fused(
    const float* __restrict__ Ah,     // current h
    const float* __restrict__ Wn,     // weight_neighbor[l]
    const float* __restrict__ Wsel,   // loop_weight[l] or evolve_loop_weight[l]
    const int*   __restrict__ list,
    const int*   __restrict__ cntp,
    float*       __restrict__ out) {

    int cnt = *cntp;
    int m0 = blockIdx.y * BM;
    if (m0 >= cnt) return;
    int n0 = blockIdx.x * BN;
    int tid = threadIdx.x;
    int tx = tid & 15;        // 0..15 -> 4 cols each
    int ty = tid >> 4;        // 0..15 -> 8 rows each

    __shared__ float As[BK][BM];
    __shared__ float Bs[BK][BN];
    __shared__ int rowid[BM];

    if (tid < BM) {
        int rl = m0 + tid;
        rowid[tid] = (rl < cnt) ? list[rl] : list[0];
    }
    __syncthreads();

    float acc[8][4];
#pragma unroll
    for (int i = 0; i < 8; i++)
#pragma unroll
        for (int j = 0; j < 4; j++) acc[i][j] = 0.f;

    int a_row = tid >> 1;          // 0..127
    int a_kk  = (tid & 1) * 4;     // 0 or 4
    int b_k   = (tid * 2) / BN;    // 0..7
    int b_n   = (tid * 2) % BN;    // even

    int ar = rowid[a_row];

#pragma unroll 1
    for (int phase = 0; phase < 2; phase++) {
        const float* A = phase ? Ah : g_agg;
        const float* B = phase ? Wsel : Wn;
        const float* arow = A + (long)ar * DD;

#pragma unroll 1
        for (int k0 = 0; k0 < DD; k0 += BK) {
            float4 av = *(const float4*)(arow + k0 + a_kk);
            int gn = n0 + b_n;
            float2 bv = make_float2(0.f, 0.f);
            if (gn < DD) bv = *(const float2*)(B + (long)(k0 + b_k) * DD + gn);

            __syncthreads();
            As[a_kk + 0][a_row] = av.x;
            As[a_kk + 1][a_row] = av.y;
            As[a_kk + 2][a_row] = av.z;
            As[a_kk + 3][a_row] = av.w;
            *(float2*)&Bs[b_k][b_n] = bv;
            __syncthreads();

#pragma unroll
            for (int k = 0; k < BK; k++) {
                float4 a0 = *(const float4*)&As[k][ty * 8 + 0];
                float4 a1 = *(const float4*)&As[k][ty * 8 + 4];
                float4 b0 = *(const float4*)&Bs[k][tx * 4];
                float af[8] = {a0.x, a0.y, a0.z, a0.w, a1.x, a1.y, a1.z, a1.w};
                float bf[4] = {b0.x, b0.y, b0.z, b0.w};
#pragma unroll
                for (int i = 0; i < 8; i++)
#pragma unroll
                    for (int j = 0; j < 4; j++) acc[i][j] += af[i] * bf[j];
            }
        }
    }

    const float slope = 0.22916666666666666f;
#pragma unroll
    for (int i = 0; i < 8; i++) {
        int rl = m0 + ty * 8 + i;
        if (rl >= cnt) continue;
        int r = rowid[ty * 8 + i];
#pragma unroll
        for (int j = 0; j < 4; j++) {
            int c = n0 + tx * 4 + j;
            if (c < DD) {
                float v = acc[i][j];
                out[(long)r * DD + c] = (v >= 0.f) ? v : v * slope;
            }
        }
    }
}

// ---------------- launch -----------------------------------------------------
extern "C" void kernel_launch(void* const* d_in, const int* in_sizes, int n_in,
                              void* d_out, int out_size) {
    const float* init_emb = (const float*)d_in[0];
    const float* rel_emb  = (const float*)d_in[1];
    const float* w_neigh  = (const float*)d_in[2];
    const float* w_loop   = (const float*)d_in[3];
    const float* w_evolve = (const float*)d_in[4];
    const float* norm     = (const float*)d_in[5];
    const int*   src      = (const int*)d_in[6];
    const int*   dst      = (const int*)d_in[7];
    const int*   etype    = (const int*)d_in[8];
    const int*   node_id  = (const int*)d_in[9];
    float* out = (float*)d_out;

    float *h0, *h1;
    int *list_in, *list_no, *cnt;
    cudaGetSymbolAddress((void**)&h0, g_h0);
    cudaGetSymbolAddress((void**)&h1, g_h1);
    cudaGetSymbolAddress((void**)&list_in, g_list_in);
    cudaGetSymbolAddress((void**)&list_no, g_list_no);
    cudaGetSymbolAddress((void**)&cnt, g_cnt);

    const int TPB = 256;
    // graph/CSR construction (depends only on inputs; recomputed each call)
    zero_k<<<(NN + TPB - 1) / TPB, TPB>>>();
    count_k<<<(EE + TPB - 1) / TPB, TPB>>>(dst);
    scan_k<<<1, 1024>>>();
    part_k<<<(NN + TPB - 1) / TPB, TPB>>>();
    fill_k<<<(EE + TPB - 1) / TPB, TPB>>>(dst);
    init_k<<<(int)(((long)NN * DD + TPB - 1) / TPB), TPB>>>(init_emb, node_id);

    dim3 ggrid((DD + BN - 1) / BN, (NN + BM - 1) / BM);

    // layer 0: h0 -> h1
    agg_k<<<NN, 256>>>(h0, rel_emb, src, etype, norm);
    gemm_fused<<<ggrid, 256>>>(h0, w_neigh + 0 * DD * DD, w_loop + 0 * DD * DD,
                               list_in, cnt + 0, h1);
    gemm_fused<<<ggrid, 256>>>(h0, w_neigh + 0 * DD * DD, w_evolve + 0 * DD * DD,
                               list_no, cnt + 1, h1);

    // layer 1: h1 -> out
    agg_k<<<NN, 256>>>(h1, rel_emb, src, etype, norm);
    gemm_fused<<<ggrid, 256>>>(h1, w_neigh + 1 * DD * DD, w_loop + 1 * DD * DD,
                               list_in, cnt + 0, out);
    gemm_fused<<<ggrid, 256>>>(h1, w_neigh + 1 * DD * DD, w_evolve + 1 * DD * DD,
                               list_no, cnt + 1, out);
}

// round 3
// speedup vs baseline: 1.6622x; 1.6622x over previous
#include <cuda_runtime.h>
#include <cuda_bf16.h>
#include <cstdint>

#define NN 50000
#define EE 800000
#define DD 200
#define KP 400           // fused K: [agg 0..199][h 200..399]
#define HOFF 200
#define BM 128
#define BN 208           // padded N (200 -> 208)
#define NKS 25           // 400/16 k-steps
#define SLOPE 0.22916666666666666f

// ---------------- scratch (static device globals) ----------------------------
__device__ float g_Af[(size_t)NN * KP];        // fused A: agg | h (fp32)
__device__ float g_hprev[(size_t)NN * DD];     // h for fixup path
__device__ float g_relagg[(size_t)NN * DD];    // layer-invariant relation sums
__device__ __nv_bfloat16 g_Bt_hi[2 * BN * KP]; // Bt[n][k] hi, n padded to 208
__device__ __nv_bfloat16 g_Bt_lo[2 * BN * KP];
__device__ int g_indeg[NN];
__device__ int g_off[NN + 1];
__device__ int g_cur[NN];
__device__ int g_src_csr[EE];
__device__ int g_et_csr[EE];
__device__ int g_list_no[NN];
__device__ int g_cnt[2];

// ---------------- helpers -----------------------------------------------------
__device__ __forceinline__ uint32_t smem_u32(const void* p) {
    uint32_t a;
    asm("{ .reg .u64 t; cvta.to.shared.u64 t, %1; cvt.u32.u64 %0, t; }" : "=r"(a) : "l"(p));
    return a;
}
__device__ __forceinline__ void ldsm4(uint32_t* r, uint32_t a) {
    asm volatile("ldmatrix.sync.aligned.m8n8.x4.shared.b16 {%0,%1,%2,%3}, [%4];"
                 : "=r"(r[0]), "=r"(r[1]), "=r"(r[2]), "=r"(r[3]) : "r"(a));
}
__device__ __forceinline__ void ldsm2(uint32_t* r, uint32_t a) {
    asm volatile("ldmatrix.sync.aligned.m8n8.x2.shared.b16 {%0,%1}, [%2];"
                 : "=r"(r[0]), "=r"(r[1]) : "r"(a));
}
__device__ __forceinline__ void mma16816(float* c, const uint32_t* a, uint32_t b0, uint32_t b1) {
    asm volatile(
        "mma.sync.aligned.m16n8k16.row.col.f32.bf16.bf16.f32 "
        "{%0,%1,%2,%3},{%4,%5,%6,%7},{%8,%9},{%0,%1,%2,%3};"
        : "+f"(c[0]), "+f"(c[1]), "+f"(c[2]), "+f"(c[3])
        : "r"(a[0]), "r"(a[1]), "r"(a[2]), "r"(a[3]), "r"(b0), "r"(b1));
}
__device__ __forceinline__ uint32_t pack_hi(float f0, float f1) {
    __nv_bfloat162 p = {__float2bfloat16(f0), __float2bfloat16(f1)};
    return *(uint32_t*)&p;
}

// ---------------- setup kernels ----------------------------------------------
__global__ void zero_k() {
    int i = blockIdx.x * blockDim.x + threadIdx.x;
    if (i < NN) g_indeg[i] = 0;
    if (i < 2) g_cnt[i] = 0;
}
__global__ void count_k(const int* __restrict__ dst) {
    int e = blockIdx.x * blockDim.x + threadIdx.x;
    if (e < EE) atomicAdd(&g_indeg[dst[e]], 1);
}
__global__ void scan_k() {
    __shared__ int sh[1024];
    __shared__ int carry;
    int tid = threadIdx.x;
    if (tid == 0) carry = 0;
    __syncthreads();
    for (int base = 0; base < NN; base += 1024) {
        int idx = base + tid;
        int v = (idx < NN) ? g_indeg[idx] : 0;
        sh[tid] = v;
        __syncthreads();
        for (int off = 1; off < 1024; off <<= 1) {
            int t = (tid >= off) ? sh[tid - off] : 0;
            __syncthreads();
            sh[tid] += t;
            __syncthreads();
        }
        int exc = sh[tid] - v;
        if (idx < NN) { g_off[idx] = carry + exc; g_cur[idx] = carry + exc; }
        __syncthreads();
        if (tid == 1023) carry += sh[1023];
        __syncthreads();
    }
    if (tid == 0) g_off[NN] = carry;
}
__global__ void part_k() {
    int i = blockIdx.x * blockDim.x + threadIdx.x;
    if (i < NN && g_indeg[i] == 0) {
        int p = atomicAdd(&g_cnt[1], 1);
        g_list_no[p] = i;
    }
}
__global__ void fill_k(const int* __restrict__ src, const int* __restrict__ dst,
                       const int* __restrict__ et) {
    int e = blockIdx.x * blockDim.x + threadIdx.x;
    if (e < EE) {
        int p = atomicAdd(&g_cur[dst[e]], 1);
        g_src_csr[p] = src[e];
        g_et_csr[p] = et[e];
    }
}
__global__ void init_k(const float* __restrict__ emb, const int* __restrict__ node_id) {
    long idx = (long)blockIdx.x * blockDim.x + threadIdx.x;
    if (idx >= (long)NN * DD) return;
    int i = (int)(idx / DD);
    int d = (int)(idx - (long)i * DD);
    float v = emb[(long)node_id[i] * DD + d];
    g_Af[(size_t)i * KP + HOFF + d] = v;
    g_hprev[idx] = v;
}
// Bt[l][n][k]: k<200 -> Wn[l][k][n]; k>=200 -> Wl[l][k-200][n]; rows n>=200 zero
__global__ void wprep_k(const float* __restrict__ wn, const float* __restrict__ wl) {
    int idx = blockIdx.x * blockDim.x + threadIdx.x;
    if (idx >= 2 * BN * KP) return;
    int l = idx / (BN * KP);
    int rem = idx - l * BN * KP;
    int n = rem / KP;
    int k = rem - n * KP;
    float w = 0.f;
    if (n < DD) {
        if (k < DD) w = wn[(size_t)l * DD * DD + k * DD + n];
        else        w = wl[(size_t)l * DD * DD + (k - DD) * DD + n];
    }
    __nv_bfloat16 hi = __float2bfloat16(w);
    float lo = w - __bfloat162float(hi);
    g_Bt_hi[idx] = hi;
    g_Bt_lo[idx] = __float2bfloat16(lo);
}

// ---------------- relation sums (once) & per-layer aggregate -----------------
__global__ void relsum_k(const float* __restrict__ rel) {
    int i = blockIdx.x, d = threadIdx.x;
    if (d >= DD) return;
    int s0 = g_off[i], s1 = g_off[i + 1];
    float a = 0.f;
    for (int p = s0; p < s1; p++) a += rel[(size_t)g_et_csr[p] * DD + d];
    g_relagg[(size_t)i * DD + d] = a;
}
__global__ void agg_k(const float* __restrict__ norm) {
    int i = blockIdx.x, d = threadIdx.x;
    if (d >= DD) return;
    int s0 = g_off[i], s1 = g_off[i + 1];
    float a = g_relagg[(size_t)i * DD + d];
    for (int p = s0; p < s1; p++) a += g_Af[(size_t)g_src_csr[p] * KP + HOFF + d];
    g_Af[(size_t)i * KP + d] = a * norm[i];
}

// ---------------- tensor-core GEMM via mma.sync (bf16 3-pass split) ----------
// C[128x200] = A[128x400] @ Bt^T, epilogue rrelu, optional write into A h-region
__global__ __launch_bounds__(256, 1) void gemm_mma(int layer, float* __restrict__ hout,
                                                   int write_next) {
    __shared__ __align__(16) __nv_bfloat16 sA[2][2][BM * 16];
    __shared__ __align__(16) __nv_bfloat16 sB[2][2][BN * 16];

    int tid = threadIdx.x;
    int lane = tid & 31, wid = tid >> 5;
    int wm = wid & 3, wn = wid >> 2;
    int m0 = blockIdx.x * BM;

    const __nv_bfloat16* __restrict__ Bh = g_Bt_hi + (size_t)layer * BN * KP;
    const __nv_bfloat16* __restrict__ Bl = g_Bt_lo + (size_t)layer * BN * KP;

    float acc[2][13][4];
#pragma unroll
    for (int i = 0; i < 2; i++)
#pragma unroll
        for (int j = 0; j < 13; j++)
#pragma unroll
            for (int q = 0; q < 4; q++) acc[i][j][q] = 0.f;

    // A loader: thread -> (row, k-half)
    int ar = tid >> 1;
    int ah = tid & 1;
    long arow = m0 + ar; if (arow >= NN) arow = 0;
    const float* aptr = g_Af + arow * KP + ah * 8;
    int asw = ar * 16 + 8 * (ah ^ ((ar >> 2) & 1));

    // B loader: two batches over 416 (row, half) units
    int br0 = tid >> 1,        bh0 = tid & 1;
    int idx1 = tid + 256;
    int br1 = idx1 >> 1,       bh1 = idx1 & 1;
    bool bp1 = idx1 < 2 * BN;
    int bsw0 = br0 * 16 + 8 * (bh0 ^ ((br0 >> 2) & 1));
    int bsw1 = br1 * 16 + 8 * (bh1 ^ ((br1 >> 2) & 1));
    if (!bp1) { br1 = 0; bh1 = 0; }

    float4 pa0, pa1;
    uint4 pbh0, pbl0, pbh1, pbl1;

    auto loadg = [&](int s) {
        int k0 = s * 16;
        pa0 = *(const float4*)(aptr + k0);
        pa1 = *(const float4*)(aptr + k0 + 4);
        pbh0 = *(const uint4*)(Bh + (size_t)br0 * KP + k0 + bh0 * 8);
        pbl0 = *(const uint4*)(Bl + (size_t)br0 * KP + k0 + bh0 * 8);
        pbh1 = *(const uint4*)(Bh + (size_t)br1 * KP + k0 + bh1 * 8);
        pbl1 = *(const uint4*)(Bl + (size_t)br1 * KP + k0 + bh1 * 8);
    };
    auto stores = [&](int st) {
        float f[8] = {pa0.x, pa0.y, pa0.z, pa0.w, pa1.x, pa1.y, pa1.z, pa1.w};
        uint32_t hw[4], lw[4];
#pragma unroll
        for (int i = 0; i < 4; i++) {
            __nv_bfloat16 h0 = __float2bfloat16(f[2 * i]);
            __nv_bfloat16 h1 = __float2bfloat16(f[2 * i + 1]);
            float l0 = f[2 * i] - __bfloat162float(h0);
            float l1 = f[2 * i + 1] - __bfloat162float(h1);
            __nv_bfloat162 ph = {h0, h1};
            __nv_bfloat162 pl = {__float2bfloat16(l0), __float2bfloat16(l1)};
            hw[i] = *(uint32_t*)&ph;
            lw[i] = *(uint32_t*)&pl;
        }
        *(uint4*)&sA[st][0][asw] = make_uint4(hw[0], hw[1], hw[2], hw[3]);
        *(uint4*)&sA[st][1][asw] = make_uint4(lw[0], lw[1], lw[2], lw[3]);
        *(uint4*)&sB[st][0][bsw0] = pbh0;
        *(uint4*)&sB[st][1][bsw0] = pbl0;
        if (bp1) {
            *(uint4*)&sB[st][0][bsw1] = pbh1;
            *(uint4*)&sB[st][1][bsw1] = pbl1;
        }
    };
    auto compute = [&](int st) {
        uint32_t baseAh = smem_u32(&sA[st][0][0]);
        uint32_t baseAl = smem_u32(&sA[st][1][0]);
        uint32_t baseBh = smem_u32(&sB[st][0][0]);
        uint32_t baseBl = smem_u32(&sB[st][1][0]);
        uint32_t fa[2][4], fal[2][4];
#pragma unroll
        for (int mi = 0; mi < 2; mi++) {
            int r = wm * 32 + mi * 16 + (lane & 15);
            int kh = lane >> 4;
            int off = r * 16 + 8 * (kh ^ ((r >> 2) & 1));
            ldsm4(fa[mi], baseAh + off * 2);
            ldsm4(fal[mi], baseAl + off * 2);
        }
#pragma unroll
        for (int pj = 0; pj < 6; pj++) {
            int rB = wn * 104 + pj * 16 + (lane & 7) + ((lane & 16) ? 8 : 0);
            int kh = (lane >> 3) & 1;
            int off = rB * 16 + 8 * (kh ^ ((rB >> 2) & 1));
            uint32_t bh[4], bl[4];
            ldsm4(bh, baseBh + off * 2);
            ldsm4(bl, baseBl + off * 2);
#pragma unroll
            for (int mi = 0; mi < 2; mi++) {
                mma16816(acc[mi][2 * pj], fa[mi], bh[0], bh[1]);
                mma16816(acc[mi][2 * pj], fal[mi], bh[0], bh[1]);
                mma16816(acc[mi][2 * pj], fa[mi], bl[0], bl[1]);
                mma16816(acc[mi][2 * pj + 1], fa[mi], bh[2], bh[3]);
                mma16816(acc[mi][2 * pj + 1], fal[mi], bh[2], bh[3]);
                mma16816(acc[mi][2 * pj + 1], fa[mi], bl[2], bl[3]);
            }
        }
        {   // tail fragment nj=12
            int rB = wn * 104 + 96 + (lane & 7) + ((lane & 16) ? 8 : 0);
            if (rB > BN - 1) rB = BN - 1;
            int kh = (lane >> 3) & 1;
            int off = rB * 16 + 8 * (kh ^ ((rB >> 2) & 1));
            uint32_t bh[2], bl[2];
            ldsm2(bh, baseBh + off * 2);
            ldsm2(bl, baseBl + off * 2);
#pragma unroll
            for (int mi = 0; mi < 2; mi++) {
                mma16816(acc[mi][12], fa[mi], bh[0], bh[1]);
                mma16816(acc[mi][12], fal[mi], bh[0], bh[1]);
                mma16816(acc[mi][12], fa[mi], bl[0], bl[1]);
            }
        }
    };

    loadg(0);
    stores(0);
    __syncthreads();
#pragma unroll 1
    for (int s = 0; s < NKS; s++) {
        int cur = s & 1;
        if (s + 1 < NKS) loadg(s + 1);
        compute(cur);
        __syncthreads();
        if (s + 1 < NKS) {
            stores(cur ^ 1);
            __syncthreads();
        }
    }

    // epilogue: rrelu, write hout and/or A h-region
    int gq = lane >> 2, tq = lane & 3;
#pragma unroll
    for (int mi = 0; mi < 2; mi++) {
        int row0 = m0 + wm * 32 + mi * 16 + gq;
        int row1 = row0 + 8;
#pragma unroll
        for (int nj = 0; nj < 13; nj++) {
            int col = wn * 104 + nj * 8 + tq * 2;
            if (col >= DD) continue;
            float v0 = acc[mi][nj][0], v1 = acc[mi][nj][1];
            float v2 = acc[mi][nj][2], v3 = acc[mi][nj][3];
            float2 p0 = {v0 >= 0.f ? v0 : v0 * SLOPE, v1 >= 0.f ? v1 : v1 * SLOPE};
            float2 p1 = {v2 >= 0.f ? v2 : v2 * SLOPE, v3 >= 0.f ? v3 : v3 * SLOPE};
            if (row0 < NN) {
                if (hout) *(float2*)(hout + (size_t)row0 * DD + col) = p0;
                if (write_next) *(float2*)(g_Af + (size_t)row0 * KP + HOFF + col) = p0;
            }
            if (row1 < NN) {
                if (hout) *(float2*)(hout + (size_t)row1 * DD + col) = p1;
                if (write_next) *(float2*)(g_Af + (size_t)row1 * KP + HOFF + col) = p1;
            }
        }
    }
}

// ---------------- fixup for indeg==0 nodes (evolve weight) -------------------
__global__ void fix_k(const float* __restrict__ wev, float* __restrict__ outbuf,
                      int write_next) {
    __shared__ float sh[DD];
    int cnt = g_cnt[1];
    for (int j = blockIdx.x; j < cnt; j += gridDim.x) {
        int r = g_list_no[j];
        for (int k = threadIdx.x; k < DD; k += blockDim.x)
            sh[k] = g_hprev[(size_t)r * DD + k];
        __syncthreads();
        int c = threadIdx.x;
        if (c < DD) {
            float a = 0.f;
            for (int k = 0; k < DD; k++) a += sh[k] * wev[k * DD + c];
            a = a >= 0.f ? a : a * SLOPE;
            if (write_next) {
                g_Af[(size_t)r * KP + HOFF + c] = a;
                g_hprev[(size_t)r * DD + c] = a;
            } else {
                outbuf[(size_t)r * DD + c] = a;
            }
        }
        __syncthreads();
    }
}

// ---------------- launch -----------------------------------------------------
extern "C" void kernel_launch(void* const* d_in, const int* in_sizes, int n_in,
                              void* d_out, int out_size) {
    const float* init_emb = (const float*)d_in[0];
    const float* rel_emb  = (const float*)d_in[1];
    const float* w_neigh  = (const float*)d_in[2];
    const float* w_loop   = (const float*)d_in[3];
    const float* w_evolve = (const float*)d_in[4];
    const float* norm     = (const float*)d_in[5];
    const int*   src      = (const int*)d_in[6];
    const int*   dst      = (const int*)d_in[7];
    const int*   etype    = (const int*)d_in[8];
    const int*   node_id  = (const int*)d_in[9];
    float* out = (float*)d_out;

    const int TPB = 256;
    zero_k<<<(NN + TPB - 1) / TPB, TPB>>>();
    count_k<<<(EE + TPB - 1) / TPB, TPB>>>(dst);
    scan_k<<<1, 1024>>>();
    part_k<<<(NN + TPB - 1) / TPB, TPB>>>();
    fill_k<<<(EE + TPB - 1) / TPB, TPB>>>(src, dst, etype);
    init_k<<<(int)(((long)NN * DD + TPB - 1) / TPB), TPB>>>(init_emb, node_id);
    wprep_k<<<(2 * BN * KP + TPB - 1) / TPB, TPB>>>(w_neigh, w_loop);
    relsum_k<<<NN, TPB>>>(rel_emb);

    int gtiles = (NN + BM - 1) / BM;  // 391

    // layer 0
    agg_k<<<NN, TPB>>>(norm);
    gemm_mma<<<gtiles, 256>>>(0, (float*)nullptr, 1);
    fix_k<<<128, TPB>>>(w_evolve + 0 * DD * DD, (float*)nullptr, 1);

    // layer 1
    agg_k<<<NN, TPB>>>(norm);
    gemm_mma<<<gtiles, 256>>>(1, out, 0);
    fix_k<<<128, TPB>>>(w_evolve + 1 * DD * DD, out, 0);
}

// round 4
// speedup vs baseline: 1.9919x; 1.1983x over previous
#include <cuda_runtime.h>
#include <cuda_bf16.h>
#include <cstdint>

#define NN 50000
#define EE 800000
#define DD 200
#define KP 400           // fused K: [agg 0..199][h 200..399]
#define HOFF 200
#define BM 128
#define BN 208
#define NKC 25           // 400/16 k-chunks
#define NT  75           // 3 passes * 25
#define SLOPE 0.22916666666666666f
#define NB 196           // ceil(NN/256)

// ---------------- scratch ----------------------------------------------------
__device__ __align__(16) __nv_bfloat16 g_Ahi[(size_t)NN * KP];
__device__ __align__(16) __nv_bfloat16 g_Alo[(size_t)NN * KP];
__device__ __align__(16) __nv_bfloat16 g_Bhi[2 * BN * KP];
__device__ __align__(16) __nv_bfloat16 g_Blo[2 * BN * KP];
__device__ float g_hprev[(size_t)NN * DD];
__device__ float g_relagg[(size_t)NN * DD];
__device__ int g_indeg[NN];
__device__ int g_off[NN + 1];
__device__ int g_cur[NN];
__device__ int g_exc[NN];
__device__ int g_bsum[NB];
__device__ int g_bpre[NB];
__device__ int g_src_csr[EE];
__device__ int g_et_csr[EE];
__device__ int g_list_no[NN];
__device__ int g_cnt[2];

// ---------------- helpers -----------------------------------------------------
__device__ __forceinline__ uint32_t smem_u32(const void* p) {
    uint32_t a;
    asm("{ .reg .u64 t; cvta.to.shared.u64 t, %1; cvt.u32.u64 %0, t; }" : "=r"(a) : "l"(p));
    return a;
}
__device__ __forceinline__ void cp16(uint32_t d, const void* s) {
    asm volatile("cp.async.cg.shared.global [%0], [%1], 16;" :: "r"(d), "l"(s));
}
#define CP_COMMIT() asm volatile("cp.async.commit_group;")
#define CP_WAIT2()  asm volatile("cp.async.wait_group 2;")
__device__ __forceinline__ void ldsm4(uint32_t* r, uint32_t a) {
    asm volatile("ldmatrix.sync.aligned.m8n8.x4.shared.b16 {%0,%1,%2,%3}, [%4];"
                 : "=r"(r[0]), "=r"(r[1]), "=r"(r[2]), "=r"(r[3]) : "r"(a));
}
__device__ __forceinline__ void ldsm2(uint32_t* r, uint32_t a) {
    asm volatile("ldmatrix.sync.aligned.m8n8.x2.shared.b16 {%0,%1}, [%2];"
                 : "=r"(r[0]), "=r"(r[1]) : "r"(a));
}
__device__ __forceinline__ void mma16816(float* c, const uint32_t* a, uint32_t b0, uint32_t b1) {
    asm volatile(
        "mma.sync.aligned.m16n8k16.row.col.f32.bf16.bf16.f32 "
        "{%0,%1,%2,%3},{%4,%5,%6,%7},{%8,%9},{%0,%1,%2,%3};"
        : "+f"(c[0]), "+f"(c[1]), "+f"(c[2]), "+f"(c[3])
        : "r"(a[0]), "r"(a[1]), "r"(a[2]), "r"(a[3]), "r"(b0), "r"(b1));
}
__device__ __forceinline__ void bf_split2(float a, float b, uint32_t& hw, uint32_t& lw) {
    __nv_bfloat16 h0 = __float2bfloat16(a), h1 = __float2bfloat16(b);
    __nv_bfloat162 ph = {h0, h1};
    __nv_bfloat162 pl = {__float2bfloat16(a - __bfloat162float(h0)),
                         __float2bfloat16(b - __bfloat162float(h1))};
    hw = *(uint32_t*)&ph;
    lw = *(uint32_t*)&pl;
}

// ---------------- setup kernels ----------------------------------------------
__global__ void zero_k() {
    int i = blockIdx.x * blockDim.x + threadIdx.x;
    if (i < NN) g_indeg[i] = 0;
    if (i < 2) g_cnt[i] = 0;
}
__global__ void count_k(const int* __restrict__ dst) {
    int e = blockIdx.x * blockDim.x + threadIdx.x;
    if (e < EE) atomicAdd(&g_indeg[dst[e]], 1);
}
// hierarchical scan
__global__ void s1_k() {
    int b = blockIdx.x, t = threadIdx.x, i = b * 256 + t;
    int v = (i < NN) ? g_indeg[i] : 0;
    int lane = t & 31, w = t >> 5;
    int x = v;
#pragma unroll
    for (int o = 1; o < 32; o <<= 1) {
        int y = __shfl_up_sync(0xffffffffu, x, o);
        if (lane >= o) x += y;
    }
    __shared__ int ws[8];
    if (lane == 31) ws[w] = x;
    __syncthreads();
    if (w == 0) {
        int s = (lane < 8) ? ws[lane] : 0;
#pragma unroll
        for (int o = 1; o < 8; o <<= 1) {
            int y = __shfl_up_sync(0xffffffffu, s, o);
            if (lane >= o) s += y;
        }
        if (lane < 8) ws[lane] = s;
    }
    __syncthreads();
    int incl = x + (w > 0 ? ws[w - 1] : 0);
    if (i < NN) g_exc[i] = incl - v;
    if (t == 255) g_bsum[b] = incl;
}
__global__ void s2_k() {
    int t = threadIdx.x;
    int v = (t < NB) ? g_bsum[t] : 0;
    int lane = t & 31, w = t >> 5;
    int x = v;
#pragma unroll
    for (int o = 1; o < 32; o <<= 1) {
        int y = __shfl_up_sync(0xffffffffu, x, o);
        if (lane >= o) x += y;
    }
    __shared__ int ws[8];
    if (lane == 31) ws[w] = x;
    __syncthreads();
    if (w == 0) {
        int s = (lane < 8) ? ws[lane] : 0;
#pragma unroll
        for (int o = 1; o < 8; o <<= 1) {
            int y = __shfl_up_sync(0xffffffffu, s, o);
            if (lane >= o) s += y;
        }
        if (lane < 8) ws[lane] = s;
    }
    __syncthreads();
    int incl = x + (w > 0 ? ws[w - 1] : 0);
    if (t < NB) g_bpre[t] = incl - v;
    if (t == NB - 1) g_off[NN] = incl;
}
__global__ void s3_k() {
    int b = blockIdx.x, t = threadIdx.x, i = b * 256 + t;
    if (i >= NN) return;
    int o = g_exc[i] + g_bpre[b];
    g_off[i] = o;
    g_cur[i] = o;
    if (g_indeg[i] == 0) {
        int p = atomicAdd(&g_cnt[1], 1);
        g_list_no[p] = i;
    }
}
__global__ void fill_k(const int* __restrict__ src, const int* __restrict__ dst,
                       const int* __restrict__ et) {
    int e = blockIdx.x * blockDim.x + threadIdx.x;
    if (e < EE) {
        int p = atomicAdd(&g_cur[dst[e]], 1);
        g_src_csr[p] = src[e];
        g_et_csr[p] = et[e];
    }
}
__global__ void init_k(const float* __restrict__ emb, const int* __restrict__ node_id) {
    long idx = (long)blockIdx.x * blockDim.x + threadIdx.x;
    if (idx >= (long)NN * (DD / 2)) return;
    int i = (int)(idx / (DD / 2));
    int c = (int)(idx - (long)i * (DD / 2)) * 2;
    const float* e = emb + (size_t)node_id[i] * DD + c;
    float v0 = e[0], v1 = e[1];
    g_hprev[(size_t)i * DD + c] = v0;
    g_hprev[(size_t)i * DD + c + 1] = v1;
    uint32_t hw, lw;
    bf_split2(v0, v1, hw, lw);
    *(uint32_t*)(g_Ahi + (size_t)i * KP + HOFF + c) = hw;
    *(uint32_t*)(g_Alo + (size_t)i * KP + HOFF + c) = lw;
}
__global__ void wprep_k(const float* __restrict__ wn, const float* __restrict__ wl) {
    int idx = blockIdx.x * blockDim.x + threadIdx.x;
    if (idx >= 2 * BN * KP) return;
    int l = idx / (BN * KP);
    int rem = idx - l * BN * KP;
    int n = rem / KP;
    int k = rem - n * KP;
    float w = 0.f;
    if (n < DD) {
        if (k < DD) w = wn[(size_t)l * DD * DD + k * DD + n];
        else        w = wl[(size_t)l * DD * DD + (k - DD) * DD + n];
    }
    __nv_bfloat16 hi = __float2bfloat16(w);
    g_Bhi[idx] = hi;
    g_Blo[idx] = __float2bfloat16(w - __bfloat162float(hi));
}

// ---------------- aggregate (layer0 fuses relation sums) ---------------------
__global__ void agg_k(const float* __restrict__ rel, const float* __restrict__ norm,
                      int first) {
    int sub = threadIdx.x >> 7;          // 2 nodes per block
    int t = threadIdx.x & 127;
    int i = blockIdx.x * 2 + sub;
    if (i >= NN || t >= DD / 2) return;
    int c = t * 2;
    int s0 = g_off[i], s1 = g_off[i + 1];
    float ar0, ar1, ah0 = 0.f, ah1 = 0.f;
    if (first) {
        ar0 = 0.f; ar1 = 0.f;
        for (int p = s0; p < s1; p++) {
            int sr = g_src_csr[p], et = g_et_csr[p];
            float2 r2 = *(const float2*)(rel + (size_t)et * DD + c);
            __nv_bfloat162 h2 = *(const __nv_bfloat162*)(g_Ahi + (size_t)sr * KP + HOFF + c);
            __nv_bfloat162 l2 = *(const __nv_bfloat162*)(g_Alo + (size_t)sr * KP + HOFF + c);
            ar0 += r2.x; ar1 += r2.y;
            ah0 += __bfloat162float(h2.x) + __bfloat162float(l2.x);
            ah1 += __bfloat162float(h2.y) + __bfloat162float(l2.y);
        }
        *(float2*)(g_relagg + (size_t)i * DD + c) = make_float2(ar0, ar1);
    } else {
        float2 r2 = *(const float2*)(g_relagg + (size_t)i * DD + c);
        ar0 = r2.x; ar1 = r2.y;
        for (int p = s0; p < s1; p++) {
            int sr = g_src_csr[p];
            __nv_bfloat162 h2 = *(const __nv_bfloat162*)(g_Ahi + (size_t)sr * KP + HOFF + c);
            __nv_bfloat162 l2 = *(const __nv_bfloat162*)(g_Alo + (size_t)sr * KP + HOFF + c);
            ah0 += __bfloat162float(h2.x) + __bfloat162float(l2.x);
            ah1 += __bfloat162float(h2.y) + __bfloat162float(l2.y);
        }
    }
    float nm = norm[i];
    uint32_t hw, lw;
    bf_split2((ar0 + ah0) * nm, (ar1 + ah1) * nm, hw, lw);
    *(uint32_t*)(g_Ahi + (size_t)i * KP + c) = hw;
    *(uint32_t*)(g_Alo + (size_t)i * KP + c) = lw;
}

// ---------------- pipelined tensor-core GEMM ---------------------------------
__global__ __launch_bounds__(256) void gemm_mma(int layer, float* __restrict__ hout,
                                                int write_next) {
    __shared__ __align__(16) __nv_bfloat16 sA[4][BM * 16];
    __shared__ __align__(16) __nv_bfloat16 sB[4][BN * 16];

    int tid = threadIdx.x;
    int lane = tid & 31, wid = tid >> 5;
    int wm = wid & 3, wn = wid >> 2;
    int m0 = blockIdx.x * BM;

    const __nv_bfloat16* __restrict__ Bh = g_Bhi + (size_t)layer * BN * KP;
    const __nv_bfloat16* __restrict__ Bl = g_Blo + (size_t)layer * BN * KP;

    float acc[2][13][4];
#pragma unroll
    for (int i = 0; i < 2; i++)
#pragma unroll
        for (int j = 0; j < 13; j++)
#pragma unroll
            for (int q = 0; q < 4; q++) acc[i][j][q] = 0.f;

    // per-thread cp.async constants
    int ar = tid >> 1, ah = tid & 1;
    long arow = m0 + ar; if (arow >= NN) arow = 0;
    size_t a_goff = (size_t)arow * KP + ah * 8;
    uint32_t a_sm = smem_u32(sA) + (uint32_t)(ar * 16 + 8 * (ah ^ ((ar >> 2) & 1))) * 2;

    int br0 = tid >> 1, bh0 = tid & 1;
    size_t b_goff0 = (size_t)br0 * KP + bh0 * 8;
    uint32_t b_sm0 = smem_u32(sB) + (uint32_t)(br0 * 16 + 8 * (bh0 ^ ((br0 >> 2) & 1))) * 2;
    int br1 = 128 + (tid >> 1), bh1 = tid & 1;
    size_t b_goff1 = (size_t)br1 * KP + bh1 * 8;
    uint32_t b_sm1 = smem_u32(sB) + (uint32_t)(br1 * 16 + 8 * (bh1 ^ ((br1 >> 2) & 1))) * 2;
    bool bp1 = tid < 160;

    auto issue = [&](int t) {
        int p = (t >= 50) ? 2 : (t >= 25 ? 1 : 0);
        int kc = t - p * 25;
        const __nv_bfloat16* As = (p == 1) ? g_Alo : g_Ahi;
        const __nv_bfloat16* Bs = (p == 2) ? Bl : Bh;
        int st = t & 3;
        long ko = (long)kc * 16;
        cp16(a_sm + st * (BM * 16 * 2), As + a_goff + ko);
        cp16(b_sm0 + st * (BN * 16 * 2), Bs + b_goff0 + ko);
        if (bp1) cp16(b_sm1 + st * (BN * 16 * 2), Bs + b_goff1 + ko);
        CP_COMMIT();
    };

    issue(0); issue(1); issue(2);

#pragma unroll 1
    for (int t = 0; t < NT; t++) {
        CP_WAIT2();
        __syncthreads();
        if (t + 3 < NT) issue(t + 3);

        int st = t & 3;
        uint32_t baseA = smem_u32(sA) + st * (BM * 16 * 2);
        uint32_t baseB = smem_u32(sB) + st * (BN * 16 * 2);
        uint32_t fa[2][4];
#pragma unroll
        for (int mi = 0; mi < 2; mi++) {
            int r = wm * 32 + mi * 16 + (lane & 15);
            int kh = lane >> 4;
            int off = r * 16 + 8 * (kh ^ ((r >> 2) & 1));
            ldsm4(fa[mi], baseA + off * 2);
        }
#pragma unroll
        for (int pj = 0; pj < 6; pj++) {
            int rB = wn * 104 + pj * 16 + (lane & 7) + ((lane & 16) ? 8 : 0);
            int kh = (lane >> 3) & 1;
            int off = rB * 16 + 8 * (kh ^ ((rB >> 2) & 1));
            uint32_t b[4];
            ldsm4(b, baseB + off * 2);
#pragma unroll
            for (int mi = 0; mi < 2; mi++) {
                mma16816(acc[mi][2 * pj], fa[mi], b[0], b[1]);
                mma16816(acc[mi][2 * pj + 1], fa[mi], b[2], b[3]);
            }
        }
        {
            int rB = wn * 104 + 96 + (lane & 7) + ((lane & 16) ? 8 : 0);
            if (rB > BN - 1) rB = BN - 1;
            int kh = (lane >> 3) & 1;
            int off = rB * 16 + 8 * (kh ^ ((rB >> 2) & 1));
            uint32_t b[2];
            ldsm2(b, baseB + off * 2);
#pragma unroll
            for (int mi = 0; mi < 2; mi++)
                mma16816(acc[mi][12], fa[mi], b[0], b[1]);
        }
    }

    // epilogue
    int gq = lane >> 2, tq = lane & 3;
#pragma unroll
    for (int mi = 0; mi < 2; mi++) {
        int row0 = m0 + wm * 32 + mi * 16 + gq;
        int row1 = row0 + 8;
#pragma unroll
        for (int nj = 0; nj < 13; nj++) {
            int col = wn * 104 + nj * 8 + tq * 2;
            if (col >= DD) continue;
            float v0 = acc[mi][nj][0], v1 = acc[mi][nj][1];
            float v2 = acc[mi][nj][2], v3 = acc[mi][nj][3];
            v0 = v0 >= 0.f ? v0 : v0 * SLOPE;
            v1 = v1 >= 0.f ? v1 : v1 * SLOPE;
            v2 = v2 >= 0.f ? v2 : v2 * SLOPE;
            v3 = v3 >= 0.f ? v3 : v3 * SLOPE;
            if (row0 < NN) {
                if (hout) *(float2*)(hout + (size_t)row0 * DD + col) = make_float2(v0, v1);
                if (write_next) {
                    uint32_t hw, lw;
                    bf_split2(v0, v1, hw, lw);
                    *(uint32_t*)(g_Ahi + (size_t)row0 * KP + HOFF + col) = hw;
                    *(uint32_t*)(g_Alo + (size_t)row0 * KP + HOFF + col) = lw;
                }
            }
            if (row1 < NN) {
                if (hout) *(float2*)(hout + (size_t)row1 * DD + col) = make_float2(v2, v3);
                if (write_next) {
                    uint32_t hw, lw;
                    bf_split2(v2, v3, hw, lw);
                    *(uint32_t*)(g_Ahi + (size_t)row1 * KP + HOFF + col) = hw;
                    *(uint32_t*)(g_Alo + (size_t)row1 * KP + HOFF + col) = lw;
                }
            }
        }
    }
}

// ---------------- fixup for indeg==0 nodes -----------------------------------
__global__ void fix_k(const float* __restrict__ wev, float* __restrict__ outbuf,
                      int write_next) {
    __shared__ float sh[DD];
    int cnt = g_cnt[1];
    for (int j = blockIdx.x; j < cnt; j += gridDim.x) {
        int r = g_list_no[j];
        for (int k = threadIdx.x; k < DD; k += blockDim.x)
            sh[k] = g_hprev[(size_t)r * DD + k];
        __syncthreads();
        int c = threadIdx.x;
        if (c < DD) {
            float a = 0.f;
            for (int k = 0; k < DD; k++) a += sh[k] * wev[k * DD + c];
            a = a >= 0.f ? a : a * SLOPE;
            if (write_next) {
                __nv_bfloat16 hi = __float2bfloat16(a);
                g_Ahi[(size_t)r * KP + HOFF + c] = hi;
                g_Alo[(size_t)r * KP + HOFF + c] = __float2bfloat16(a - __bfloat162float(hi));
                g_hprev[(size_t)r * DD + c] = a;
            } else {
                outbuf[(size_t)r * DD + c] = a;
            }
        }
        __syncthreads();
    }
}

// ---------------- launch -----------------------------------------------------
extern "C" void kernel_launch(void* const* d_in, const int* in_sizes, int n_in,
                              void* d_out, int out_size) {
    const float* init_emb = (const float*)d_in[0];
    const float* rel_emb  = (const float*)d_in[1];
    const float* w_neigh  = (const float*)d_in[2];
    const float* w_loop   = (const float*)d_in[3];
    const float* w_evolve = (const float*)d_in[4];
    const float* norm     = (const float*)d_in[5];
    const int*   src      = (const int*)d_in[6];
    const int*   dst      = (const int*)d_in[7];
    const int*   etype    = (const int*)d_in[8];
    const int*   node_id  = (const int*)d_in[9];
    float* out = (float*)d_out;

    const int TPB = 256;
    zero_k<<<(NN + TPB - 1) / TPB, TPB>>>();
    count_k<<<(EE + TPB - 1) / TPB, TPB>>>(dst);
    s1_k<<<NB, 256>>>();
    s2_k<<<1, 256>>>();
    s3_k<<<NB, 256>>>();
    fill_k<<<(EE + TPB - 1) / TPB, TPB>>>(src, dst, etype);
    init_k<<<(int)(((long)NN * (DD / 2) + TPB - 1) / TPB), TPB>>>(init_emb, node_id);
    wprep_k<<<(2 * BN * KP + TPB - 1) / TPB, TPB>>>(w_neigh, w_loop);

    int gtiles = (NN + BM - 1) / BM;   // 391
    int agrid = (NN + 1) / 2;

    // layer 0
    agg_k<<<agrid, 256>>>(rel_emb, norm, 1);
    gemm_mma<<<gtiles, 256>>>(0, (float*)nullptr, 1);
    fix_k<<<128, TPB>>>(w_evolve + 0 * DD * DD, (float*)nullptr, 1);

    // layer 1
    agg_k<<<agrid, 256>>>(rel_emb, norm, 0);
    gemm_mma<<<gtiles, 256>>>(1, out, 0);
    fix_k<<<128, TPB>>>(w_evolve + 1 * DD * DD, out, 0);
}

// round 7
// speedup vs baseline: 3.0221x; 1.5172x over previous
#include <cuda_runtime.h>
#include <cuda_fp16.h>
#include <cstdint>

#define NN 50000
#define EE 800000
#define DD 200
#define KP 400           // fused K: [agg 0..199][h 200..399]
#define HOFF 200
#define BM 128
#define BN 208
#define NT 50            // 2 passes * 25 k-chunks
#define SLOPE 0.22916666666666666f
#define NB 196           // ceil(NN/256)

// ---------------- scratch (zero-initialized at load; invariants restored) ----
__device__ __align__(16) __half g_Af16[(size_t)NN * KP];   // fp16 A: agg | h
__device__ __align__(16) __half g_Bh16[2 * BN * KP];       // weight hi
__device__ __align__(16) __half g_Bl16[2 * BN * KP];       // weight lo
__device__ float g_hf[(size_t)NN * DD];                    // fp32 h (gather/fix)
__device__ float g_relagg[(size_t)NN * DD];
__device__ int g_indeg[NN];          // zero at entry (restored by s3_k)
__device__ int g_off[NN + 1];
__device__ int g_cur[NN];
__device__ int g_exc[NN];
__device__ int g_bsum[NB];
__device__ int g_bpre[NB];
__device__ unsigned int g_csr[EE];   // src | (etype<<16)
__device__ int g_list_no[NN];
__device__ int g_cnt[2];             // zero at entry (restored by cleanup_k)

// ---------------- helpers -----------------------------------------------------
__device__ __forceinline__ uint32_t smem_u32(const void* p) {
    uint32_t a;
    asm("{ .reg .u64 t; cvta.to.shared.u64 t, %1; cvt.u32.u64 %0, t; }" : "=r"(a) : "l"(p));
    return a;
}
__device__ __forceinline__ void cp16(uint32_t d, const void* s) {
    asm volatile("cp.async.cg.shared.global [%0], [%1], 16;" :: "r"(d), "l"(s));
}
#define CP_COMMIT() asm volatile("cp.async.commit_group;")
#define CP_WAIT2()  asm volatile("cp.async.wait_group 2;")
__device__ __forceinline__ void ldsm4(uint32_t* r, uint32_t a) {
    asm volatile("ldmatrix.sync.aligned.m8n8.x4.shared.b16 {%0,%1,%2,%3}, [%4];"
                 : "=r"(r[0]), "=r"(r[1]), "=r"(r[2]), "=r"(r[3]) : "r"(a));
}
__device__ __forceinline__ void ldsm2(uint32_t* r, uint32_t a) {
    asm volatile("ldmatrix.sync.aligned.m8n8.x2.shared.b16 {%0,%1}, [%2];"
                 : "=r"(r[0]), "=r"(r[1]) : "r"(a));
}
__device__ __forceinline__ void mma16816(float* c, const uint32_t* a, uint32_t b0, uint32_t b1) {
    asm volatile(
        "mma.sync.aligned.m16n8k16.row.col.f32.f16.f16.f32 "
        "{%0,%1,%2,%3},{%4,%5,%6,%7},{%8,%9},{%0,%1,%2,%3};"
        : "+f"(c[0]), "+f"(c[1]), "+f"(c[2]), "+f"(c[3])
        : "r"(a[0]), "r"(a[1]), "r"(a[2]), "r"(a[3]), "r"(b0), "r"(b1));
}

// ---------------- setup kernels ----------------------------------------------
__global__ void count_k(const int* __restrict__ dst) {
    int e = blockIdx.x * blockDim.x + threadIdx.x;
    if (e < EE) atomicAdd(&g_indeg[dst[e]], 1);
}
__global__ void s1_k() {
    int b = blockIdx.x, t = threadIdx.x, i = b * 256 + t;
    int v = (i < NN) ? g_indeg[i] : 0;
    int lane = t & 31, w = t >> 5;
    int x = v;
#pragma unroll
    for (int o = 1; o < 32; o <<= 1) {
        int y = __shfl_up_sync(0xffffffffu, x, o);
        if (lane >= o) x += y;
    }
    __shared__ int ws[8];
    if (lane == 31) ws[w] = x;
    __syncthreads();
    if (w == 0) {
        int s = (lane < 8) ? ws[lane] : 0;
#pragma unroll
        for (int o = 1; o < 8; o <<= 1) {
            int y = __shfl_up_sync(0xffffffffu, s, o);
            if (lane >= o) s += y;
        }
        if (lane < 8) ws[lane] = s;
    }
    __syncthreads();
    int incl = x + (w > 0 ? ws[w - 1] : 0);
    if (i < NN) g_exc[i] = incl - v;
    if (t == 255) g_bsum[b] = incl;
}
__global__ void s2_k() {
    int t = threadIdx.x;
    int v = (t < NB) ? g_bsum[t] : 0;
    int lane = t & 31, w = t >> 5;
    int x = v;
#pragma unroll
    for (int o = 1; o < 32; o <<= 1) {
        int y = __shfl_up_sync(0xffffffffu, x, o);
        if (lane >= o) x += y;
    }
    __shared__ int ws[8];
    if (lane == 31) ws[w] = x;
    __syncthreads();
    if (w == 0) {
        int s = (lane < 8) ? ws[lane] : 0;
#pragma unroll
        for (int o = 1; o < 8; o <<= 1) {
            int y = __shfl_up_sync(0xffffffffu, s, o);
            if (lane >= o) s += y;
        }
        if (lane < 8) ws[lane] = s;
    }
    __syncthreads();
    int incl = x + (w > 0 ? ws[w - 1] : 0);
    if (t < NB) g_bpre[t] = incl - v;
    if (t == NB - 1) g_off[NN] = incl;
}
__global__ void s3_k() {
    int b = blockIdx.x, t = threadIdx.x, i = b * 256 + t;
    if (i >= NN) return;
    int o = g_exc[i] + g_bpre[b];
    g_off[i] = o;
    g_cur[i] = o;
    if (g_indeg[i] == 0) {
        int p = atomicAdd(&g_cnt[1], 1);
        g_list_no[p] = i;
    }
    g_indeg[i] = 0;   // restore invariant for next call
}
// fused: fill (CSR) + init (h, A h-region) + wprep (weight split)
#define FILL_B 3125
#define INIT_B 19532
#define WPREP_B 650
__global__ void setup_k(const int* __restrict__ src, const int* __restrict__ dst,
                        const int* __restrict__ et,
                        const float* __restrict__ emb, const int* __restrict__ node_id,
                        const float* __restrict__ wn, const float* __restrict__ wl) {
    int b = blockIdx.x;
    if (b < FILL_B) {
        int e = b * 256 + threadIdx.x;
        if (e < EE) {
            int p = atomicAdd(&g_cur[dst[e]], 1);
            g_csr[p] = (unsigned int)src[e] | ((unsigned int)et[e] << 16);
        }
    } else if (b < FILL_B + INIT_B) {
        long idx = (long)(b - FILL_B) * 256 + threadIdx.x;
        if (idx >= (long)NN * (DD / 2)) return;
        int i = (int)(idx / (DD / 2));
        int c = (int)(idx - (long)i * (DD / 2)) * 2;
        const float* e = emb + (size_t)node_id[i] * DD + c;
        float v0 = e[0], v1 = e[1];
        *(float2*)(g_hf + (size_t)i * DD + c) = make_float2(v0, v1);
        *(half2*)(g_Af16 + (size_t)i * KP + HOFF + c) = __floats2half2_rn(v0, v1);
    } else {
        int idx = (b - FILL_B - INIT_B) * 256 + threadIdx.x;
        if (idx >= 2 * BN * KP) return;
        int l = idx / (BN * KP);
        int rem = idx - l * BN * KP;
        int n = rem / KP;
        int k = rem - n * KP;
        float w = 0.f;
        if (n < DD) {
            if (k < DD) w = wn[(size_t)l * DD * DD + k * DD + n];
            else        w = wl[(size_t)l * DD * DD + (k - DD) * DD + n];
        }
        __half hi = __float2half_rn(w);
        g_Bh16[idx] = hi;
        g_Bl16[idx] = __float2half_rn(w - __half2float(hi));
    }
}

// ---------------- aggregate (layer0 fuses relation sums) ---------------------
__global__ void agg_k(const float* __restrict__ rel, const float* __restrict__ norm,
                      int first) {
    int sub = threadIdx.x >> 7;
    int t = threadIdx.x & 127;
    int i = blockIdx.x * 2 + sub;
    if (i >= NN || t >= DD / 2) return;
    int c = t * 2;
    int s0 = g_off[i], s1 = g_off[i + 1];
    float a0, a1;
    if (first) {
        float r0 = 0.f, r1 = 0.f, h0 = 0.f, h1 = 0.f;
        for (int p = s0; p < s1; p++) {
            unsigned int pe = g_csr[p];
            int sr = pe & 0xFFFF, e = pe >> 16;
            float2 r2 = *(const float2*)(rel + (size_t)e * DD + c);
            float2 h2 = *(const float2*)(g_hf + (size_t)sr * DD + c);
            r0 += r2.x; r1 += r2.y;
            h0 += h2.x; h1 += h2.y;
        }
        *(float2*)(g_relagg + (size_t)i * DD + c) = make_float2(r0, r1);
        a0 = r0 + h0; a1 = r1 + h1;
    } else {
        float2 r2 = *(const float2*)(g_relagg + (size_t)i * DD + c);
        a0 = r2.x; a1 = r2.y;
        for (int p = s0; p < s1; p++) {
            int sr = g_csr[p] & 0xFFFF;
            float2 h2 = *(const float2*)(g_hf + (size_t)sr * DD + c);
            a0 += h2.x; a1 += h2.y;
        }
    }
    float nm = norm[i];
    *(half2*)(g_Af16 + (size_t)i * KP + c) = __floats2half2_rn(a0 * nm, a1 * nm);
}

// ---------------- pipelined tensor-core GEMM (fp16 2-pass) -------------------
__global__ __launch_bounds__(256) void gemm_mma(int layer, float* __restrict__ hout,
                                                int write_next) {
    __shared__ __align__(16) __half sA[4][BM * 16];
    __shared__ __align__(16) __half sB[4][BN * 16];

    int tid = threadIdx.x;
    int lane = tid & 31, wid = tid >> 5;
    int wm = wid & 3, wn = wid >> 2;
    int m0 = blockIdx.x * BM;

    const __half* __restrict__ Bh = g_Bh16 + (size_t)layer * BN * KP;
    const __half* __restrict__ Bl = g_Bl16 + (size_t)layer * BN * KP;

    float acc[2][13][4];
#pragma unroll
    for (int i = 0; i < 2; i++)
#pragma unroll
        for (int j = 0; j < 13; j++)
#pragma unroll
            for (int q = 0; q < 4; q++) acc[i][j][q] = 0.f;

    int ar = tid >> 1, ah = tid & 1;
    long arow = m0 + ar; if (arow >= NN) arow = 0;
    size_t a_goff = (size_t)arow * KP + ah * 8;
    uint32_t a_sm = smem_u32(sA) + (uint32_t)(ar * 16 + 8 * (ah ^ ((ar >> 2) & 1))) * 2;

    int br0 = tid >> 1, bh0 = tid & 1;
    size_t b_goff0 = (size_t)br0 * KP + bh0 * 8;
    uint32_t b_sm0 = smem_u32(sB) + (uint32_t)(br0 * 16 + 8 * (bh0 ^ ((br0 >> 2) & 1))) * 2;
    int br1 = 128 + (tid >> 1), bh1 = tid & 1;
    size_t b_goff1 = (size_t)br1 * KP + bh1 * 8;
    uint32_t b_sm1 = smem_u32(sB) + (uint32_t)(br1 * 16 + 8 * (bh1 ^ ((br1 >> 2) & 1))) * 2;
    bool bp1 = tid < 160;

    auto issue = [&](int t) {
        int p = (t >= 25) ? 1 : 0;
        int kc = t - p * 25;
        const __half* Bs = p ? Bl : Bh;
        int st = t & 3;
        long ko = (long)kc * 16;
        cp16(a_sm + st * (BM * 16 * 2), g_Af16 + a_goff + ko);
        cp16(b_sm0 + st * (BN * 16 * 2), Bs + b_goff0 + ko);
        if (bp1) cp16(b_sm1 + st * (BN * 16 * 2), Bs + b_goff1 + ko);
        CP_COMMIT();
    };

    issue(0); issue(1); issue(2);

#pragma unroll 1
    for (int t = 0; t < NT; t++) {
        CP_WAIT2();
        __syncthreads();
        if (t + 3 < NT) issue(t + 3);

        int st = t & 3;
        uint32_t baseA = smem_u32(sA) + st * (BM * 16 * 2);
        uint32_t baseB = smem_u32(sB) + st * (BN * 16 * 2);
        uint32_t fa[2][4];
#pragma unroll
        for (int mi = 0; mi < 2; mi++) {
            int r = wm * 32 + mi * 16 + (lane & 15);
            int kh = lane >> 4;
            int off = r * 16 + 8 * (kh ^ ((r >> 2) & 1));
            ldsm4(fa[mi], baseA + off * 2);
        }
#pragma unroll
        for (int pj = 0; pj < 6; pj++) {
            int rB = wn * 104 + pj * 16 + (lane & 7) + ((lane & 16) ? 8 : 0);
            int kh = (lane >> 3) & 1;
            int off = rB * 16 + 8 * (kh ^ ((rB >> 2) & 1));
            uint32_t b[4];
            ldsm4(b, baseB + off * 2);
#pragma unroll
            for (int mi = 0; mi < 2; mi++) {
                mma16816(acc[mi][2 * pj], fa[mi], b[0], b[1]);
                mma16816(acc[mi][2 * pj + 1], fa[mi], b[2], b[3]);
            }
        }
        {
            int rB = wn * 104 + 96 + (lane & 7) + ((lane & 16) ? 8 : 0);
            if (rB > BN - 1) rB = BN - 1;
            int kh = (lane >> 3) & 1;
            int off = rB * 16 + 8 * (kh ^ ((rB >> 2) & 1));
            uint32_t b[2];
            ldsm2(b, baseB + off * 2);
#pragma unroll
            for (int mi = 0; mi < 2; mi++)
                mma16816(acc[mi][12], fa[mi], b[0], b[1]);
        }
    }

    // epilogue: rrelu; layer0 -> g_hf + A fp16; layer1 -> out
    int gq = lane >> 2, tq = lane & 3;
#pragma unroll
    for (int mi = 0; mi < 2; mi++) {
        int row0 = m0 + wm * 32 + mi * 16 + gq;
        int row1 = row0 + 8;
#pragma unroll
        for (int nj = 0; nj < 13; nj++) {
            int col = wn * 104 + nj * 8 + tq * 2;
            if (col >= DD) continue;
            float v0 = acc[mi][nj][0], v1 = acc[mi][nj][1];
            float v2 = acc[mi][nj][2], v3 = acc[mi][nj][3];
            v0 = v0 >= 0.f ? v0 : v0 * SLOPE;
            v1 = v1 >= 0.f ? v1 : v1 * SLOPE;
            v2 = v2 >= 0.f ? v2 : v2 * SLOPE;
            v3 = v3 >= 0.f ? v3 : v3 * SLOPE;
            if (row0 < NN) {
                if (hout) *(float2*)(hout + (size_t)row0 * DD + col) = make_float2(v0, v1);
                if (write_next) {
                    *(float2*)(g_hf + (size_t)row0 * DD + col) = make_float2(v0, v1);
                    *(half2*)(g_Af16 + (size_t)row0 * KP + HOFF + col) = __floats2half2_rn(v0, v1);
                }
            }
            if (row1 < NN) {
                if (hout) *(float2*)(hout + (size_t)row1 * DD + col) = make_float2(v2, v3);
                if (write_next) {
                    *(float2*)(g_hf + (size_t)row1 * DD + col) = make_float2(v2, v3);
                    *(half2*)(g_Af16 + (size_t)row1 * KP + HOFF + col) = __floats2half2_rn(v2, v3);
                }
            }
        }
    }
}

// ---------------- fixup for indeg==0 nodes -----------------------------------
__global__ void fix_k(const float* __restrict__ wev, float* __restrict__ outbuf,
                      int write_next) {
    __shared__ float sh[DD];
    int cnt = g_cnt[1];
    for (int j = blockIdx.x; j < cnt; j += gridDim.x) {
        int r = g_list_no[j];
        for (int k = threadIdx.x; k < DD; k += blockDim.x)
            sh[k] = g_hf[(size_t)r * DD + k];
        __syncthreads();
        int c = threadIdx.x;
        if (c < DD) {
            float a = 0.f;
            for (int k = 0; k < DD; k++) a += sh[k] * wev[k * DD + c];
            a = a >= 0.f ? a : a * SLOPE;
            if (write_next) {
                g_hf[(size_t)r * DD + c] = a;
                g_Af16[(size_t)r * KP + HOFF + c] = __float2half_rn(a);
            } else {
                outbuf[(size_t)r * DD + c] = a;
            }
        }
        __syncthreads();
    }
}
__global__ void cleanup_k() {
    if (threadIdx.x < 2) g_cnt[threadIdx.x] = 0;
}

// ---------------- launch -----------------------------------------------------
extern "C" void kernel_launch(void* const* d_in, const int* in_sizes, int n_in,
                              void* d_out, int out_size) {
    const float* init_emb = (const float*)d_in[0];
    const float* rel_emb  = (const float*)d_in[1];
    const float* w_neigh  = (const float*)d_in[2];
    const float* w_loop   = (const float*)d_in[3];
    const float* w_evolve = (const float*)d_in[4];
    const float* norm     = (const float*)d_in[5];
    const int*   src      = (const int*)d_in[6];
    const int*   dst      = (const int*)d_in[7];
    const int*   etype    = (const int*)d_in[8];
    const int*   node_id  = (const int*)d_in[9];
    float* out = (float*)d_out;

    count_k<<<(EE + 255) / 256, 256>>>(dst);                      // 0
    s1_k<<<NB, 256>>>();                                          // 1
    s2_k<<<1, 256>>>();                                           // 2
    s3_k<<<NB, 256>>>();                                          // 3
    setup_k<<<FILL_B + INIT_B + WPREP_B, 256>>>(src, dst, etype,  // 4
                                                init_emb, node_id, w_neigh, w_loop);

    int gtiles = (NN + BM - 1) / BM;
    int agrid = (NN + 1) / 2;

    agg_k<<<agrid, 256>>>(rel_emb, norm, 1);                      // 5  <- profiled
    gemm_mma<<<gtiles, 256>>>(0, (float*)nullptr, 1);             // 6
    fix_k<<<128, 256>>>(w_evolve + 0 * DD * DD, (float*)nullptr, 1);
    agg_k<<<agrid, 256>>>(rel_emb, norm, 0);
    gemm_mma<<<gtiles, 256>>>(1, out, 0);
    fix_k<<<128, 256>>>(w_evolve + 1 * DD * DD, out, 0);
    cleanup_k<<<1, 32>>>();
}

// round 8
// speedup vs baseline: 3.5317x; 1.1686x over previous
#include <cuda_runtime.h>
#include <cuda_fp16.h>
#include <cstdint>

#define NN 50000
#define EE 800000
#define DD 200
#define KP 400           // fused K: [agg 0..199][h 200..399]
#define HOFF 200
#define BM 128
#define BN 208
#define NT 25            // 25 k-chunks (single fp16 pass)
#define SLOPE 0.22916666666666666f
#define NB 196           // ceil(NN/256)

// ---------------- scratch (zero-initialized at load; invariants restored) ----
__device__ __align__(16) __half g_Af16[(size_t)NN * KP];   // fp16 A: agg | h
__device__ __align__(16) __half g_B16[2 * BN * KP];        // fp16 weights (fused, transposed)
__device__ float g_relagg[(size_t)NN * DD];
__device__ float g_fixbuf[(size_t)NN * DD];
__device__ int g_indeg[NN];          // zero at entry (restored by s3_k)
__device__ int g_off[NN + 1];
__device__ int g_cur[NN];
__device__ int g_exc[NN];
__device__ int g_bsum[NB];
__device__ int g_bpre[NB];
__device__ unsigned int g_csr[EE];   // src | (etype<<16)
__device__ int g_list_no[NN];
__device__ int g_cnt[2];             // zero at entry (restored by cleanup_k)

// ---------------- helpers -----------------------------------------------------
__device__ __forceinline__ uint32_t smem_u32(const void* p) {
    uint32_t a;
    asm("{ .reg .u64 t; cvta.to.shared.u64 t, %1; cvt.u32.u64 %0, t; }" : "=r"(a) : "l"(p));
    return a;
}
__device__ __forceinline__ void cp16(uint32_t d, const void* s) {
    asm volatile("cp.async.cg.shared.global [%0], [%1], 16;" :: "r"(d), "l"(s));
}
#define CP_COMMIT() asm volatile("cp.async.commit_group;")
#define CP_WAIT2()  asm volatile("cp.async.wait_group 2;")
__device__ __forceinline__ void ldsm4(uint32_t* r, uint32_t a) {
    asm volatile("ldmatrix.sync.aligned.m8n8.x4.shared.b16 {%0,%1,%2,%3}, [%4];"
                 : "=r"(r[0]), "=r"(r[1]), "=r"(r[2]), "=r"(r[3]) : "r"(a));
}
__device__ __forceinline__ void ldsm2(uint32_t* r, uint32_t a) {
    asm volatile("ldmatrix.sync.aligned.m8n8.x2.shared.b16 {%0,%1}, [%2];"
                 : "=r"(r[0]), "=r"(r[1]) : "r"(a));
}
__device__ __forceinline__ void mma16816(float* c, const uint32_t* a, uint32_t b0, uint32_t b1) {
    asm volatile(
        "mma.sync.aligned.m16n8k16.row.col.f32.f16.f16.f32 "
        "{%0,%1,%2,%3},{%4,%5,%6,%7},{%8,%9},{%0,%1,%2,%3};"
        : "+f"(c[0]), "+f"(c[1]), "+f"(c[2]), "+f"(c[3])
        : "r"(a[0]), "r"(a[1]), "r"(a[2]), "r"(a[3]), "r"(b0), "r"(b1));
}

// ---------------- setup kernels ----------------------------------------------
__global__ void count_k(const int* __restrict__ dst) {
    int e = blockIdx.x * blockDim.x + threadIdx.x;
    if (e < EE) atomicAdd(&g_indeg[dst[e]], 1);
}
__global__ void s1_k() {
    int b = blockIdx.x, t = threadIdx.x, i = b * 256 + t;
    int v = (i < NN) ? g_indeg[i] : 0;
    int lane = t & 31, w = t >> 5;
    int x = v;
#pragma unroll
    for (int o = 1; o < 32; o <<= 1) {
        int y = __shfl_up_sync(0xffffffffu, x, o);
        if (lane >= o) x += y;
    }
    __shared__ int ws[8];
    if (lane == 31) ws[w] = x;
    __syncthreads();
    if (w == 0) {
        int s = (lane < 8) ? ws[lane] : 0;
#pragma unroll
        for (int o = 1; o < 8; o <<= 1) {
            int y = __shfl_up_sync(0xffffffffu, s, o);
            if (lane >= o) s += y;
        }
        if (lane < 8) ws[lane] = s;
    }
    __syncthreads();
    int incl = x + (w > 0 ? ws[w - 1] : 0);
    if (i < NN) g_exc[i] = incl - v;
    if (t == 255) g_bsum[b] = incl;
}
__global__ void s2_k() {
    int t = threadIdx.x;
    int v = (t < NB) ? g_bsum[t] : 0;
    int lane = t & 31, w = t >> 5;
    int x = v;
#pragma unroll
    for (int o = 1; o < 32; o <<= 1) {
        int y = __shfl_up_sync(0xffffffffu, x, o);
        if (lane >= o) x += y;
    }
    __shared__ int ws[8];
    if (lane == 31) ws[w] = x;
    __syncthreads();
    if (w == 0) {
        int s = (lane < 8) ? ws[lane] : 0;
#pragma unroll
        for (int o = 1; o < 8; o <<= 1) {
            int y = __shfl_up_sync(0xffffffffu, s, o);
            if (lane >= o) s += y;
        }
        if (lane < 8) ws[lane] = s;
    }
    __syncthreads();
    int incl = x + (w > 0 ? ws[w - 1] : 0);
    if (t < NB) g_bpre[t] = incl - v;
    if (t == NB - 1) g_off[NN] = incl;
}
__global__ void s3_k() {
    int b = blockIdx.x, t = threadIdx.x, i = b * 256 + t;
    if (i >= NN) return;
    int o = g_exc[i] + g_bpre[b];
    g_off[i] = o;
    g_cur[i] = o;
    if (g_indeg[i] == 0) {
        int p = atomicAdd(&g_cnt[1], 1);
        g_list_no[p] = i;
    }
    g_indeg[i] = 0;   // restore invariant for next call
}
// fused: fill (CSR) + init (A h-region) + wprep (fp16 weights)
#define FILL_B 3125
#define INIT_B 19532
#define WPREP_B 650
__global__ void setup_k(const int* __restrict__ src, const int* __restrict__ dst,
                        const int* __restrict__ et,
                        const float* __restrict__ emb, const int* __restrict__ node_id,
                        const float* __restrict__ wn, const float* __restrict__ wl) {
    int b = blockIdx.x;
    if (b < FILL_B) {
        int e = b * 256 + threadIdx.x;
        if (e < EE) {
            int p = atomicAdd(&g_cur[dst[e]], 1);
            g_csr[p] = (unsigned int)src[e] | ((unsigned int)et[e] << 16);
        }
    } else if (b < FILL_B + INIT_B) {
        long idx = (long)(b - FILL_B) * 256 + threadIdx.x;
        if (idx >= (long)NN * (DD / 2)) return;
        int i = (int)(idx / (DD / 2));
        int c = (int)(idx - (long)i * (DD / 2)) * 2;
        const float* e = emb + (size_t)node_id[i] * DD + c;
        *(half2*)(g_Af16 + (size_t)i * KP + HOFF + c) = __floats2half2_rn(e[0], e[1]);
    } else {
        int idx = (b - FILL_B - INIT_B) * 256 + threadIdx.x;
        if (idx >= 2 * BN * KP) return;
        int l = idx / (BN * KP);
        int rem = idx - l * BN * KP;
        int n = rem / KP;
        int k = rem - n * KP;
        float w = 0.f;
        if (n < DD) {
            if (k < DD) w = wn[(size_t)l * DD * DD + k * DD + n];
            else        w = wl[(size_t)l * DD * DD + (k - DD) * DD + n];
        }
        g_B16[idx] = __float2half_rn(w);
    }
}

// ---------------- aggregate (fp16 gather; layer0 fuses relation sums) --------
__global__ void agg_k(const float* __restrict__ rel, const float* __restrict__ norm,
                      int first) {
    int sub = threadIdx.x >> 7;
    int t = threadIdx.x & 127;
    int i = blockIdx.x * 2 + sub;
    if (i >= NN || t >= DD / 2) return;
    int c = t * 2;
    int s0 = g_off[i], s1 = g_off[i + 1];
    float a0, a1;
    if (first) {
        float r0 = 0.f, r1 = 0.f, h0 = 0.f, h1 = 0.f;
        for (int p = s0; p < s1; p++) {
            unsigned int pe = g_csr[p];
            int sr = pe & 0xFFFF, e = pe >> 16;
            float2 r2 = *(const float2*)(rel + (size_t)e * DD + c);
            float2 h2 = __half22float2(*(const half2*)(g_Af16 + (size_t)sr * KP + HOFF + c));
            r0 += r2.x; r1 += r2.y;
            h0 += h2.x; h1 += h2.y;
        }
        *(float2*)(g_relagg + (size_t)i * DD + c) = make_float2(r0, r1);
        a0 = r0 + h0; a1 = r1 + h1;
    } else {
        float2 r2 = *(const float2*)(g_relagg + (size_t)i * DD + c);
        a0 = r2.x; a1 = r2.y;
        for (int p = s0; p < s1; p++) {
            int sr = g_csr[p] & 0xFFFF;
            float2 h2 = __half22float2(*(const half2*)(g_Af16 + (size_t)sr * KP + HOFF + c));
            a0 += h2.x; a1 += h2.y;
        }
    }
    float nm = norm[i];
    *(half2*)(g_Af16 + (size_t)i * KP + c) = __floats2half2_rn(a0 * nm, a1 * nm);
}

// ---------------- pipelined tensor-core GEMM (fp16 single pass) --------------
__global__ __launch_bounds__(256) void gemm_mma(int layer, float* __restrict__ hout,
                                                int write_next) {
    __shared__ __align__(16) __half sA[4][BM * 16];
    __shared__ __align__(16) __half sB[4][BN * 16];

    int tid = threadIdx.x;
    int lane = tid & 31, wid = tid >> 5;
    int wm = wid & 3, wn = wid >> 2;
    int m0 = blockIdx.x * BM;

    const __half* __restrict__ Bw = g_B16 + (size_t)layer * BN * KP;

    float acc[2][13][4];
#pragma unroll
    for (int i = 0; i < 2; i++)
#pragma unroll
        for (int j = 0; j < 13; j++)
#pragma unroll
            for (int q = 0; q < 4; q++) acc[i][j][q] = 0.f;

    int ar = tid >> 1, ah = tid & 1;
    long arow = m0 + ar; if (arow >= NN) arow = 0;
    size_t a_goff = (size_t)arow * KP + ah * 8;
    uint32_t a_sm = smem_u32(sA) + (uint32_t)(ar * 16 + 8 * (ah ^ ((ar >> 2) & 1))) * 2;

    int br0 = tid >> 1, bh0 = tid & 1;
    size_t b_goff0 = (size_t)br0 * KP + bh0 * 8;
    uint32_t b_sm0 = smem_u32(sB) + (uint32_t)(br0 * 16 + 8 * (bh0 ^ ((br0 >> 2) & 1))) * 2;
    int br1 = 128 + (tid >> 1), bh1 = tid & 1;
    size_t b_goff1 = (size_t)br1 * KP + bh1 * 8;
    uint32_t b_sm1 = smem_u32(sB) + (uint32_t)(br1 * 16 + 8 * (bh1 ^ ((br1 >> 2) & 1))) * 2;
    bool bp1 = tid < 160;

    auto issue = [&](int t) {
        int st = t & 3;
        long ko = (long)t * 16;
        cp16(a_sm + st * (BM * 16 * 2), g_Af16 + a_goff + ko);
        cp16(b_sm0 + st * (BN * 16 * 2), Bw + b_goff0 + ko);
        if (bp1) cp16(b_sm1 + st * (BN * 16 * 2), Bw + b_goff1 + ko);
        CP_COMMIT();
    };

    issue(0); issue(1); issue(2);

#pragma unroll 1
    for (int t = 0; t < NT; t++) {
        CP_WAIT2();
        __syncthreads();
        if (t + 3 < NT) issue(t + 3);

        int st = t & 3;
        uint32_t baseA = smem_u32(sA) + st * (BM * 16 * 2);
        uint32_t baseB = smem_u32(sB) + st * (BN * 16 * 2);
        uint32_t fa[2][4];
#pragma unroll
        for (int mi = 0; mi < 2; mi++) {
            int r = wm * 32 + mi * 16 + (lane & 15);
            int kh = lane >> 4;
            int off = r * 16 + 8 * (kh ^ ((r >> 2) & 1));
            ldsm4(fa[mi], baseA + off * 2);
        }
#pragma unroll
        for (int pj = 0; pj < 6; pj++) {
            int rB = wn * 104 + pj * 16 + (lane & 7) + ((lane & 16) ? 8 : 0);
            int kh = (lane >> 3) & 1;
            int off = rB * 16 + 8 * (kh ^ ((rB >> 2) & 1));
            uint32_t b[4];
            ldsm4(b, baseB + off * 2);
#pragma unroll
            for (int mi = 0; mi < 2; mi++) {
                mma16816(acc[mi][2 * pj], fa[mi], b[0], b[1]);
                mma16816(acc[mi][2 * pj + 1], fa[mi], b[2], b[3]);
            }
        }
        {
            int rB = wn * 104 + 96 + (lane & 7) + ((lane & 16) ? 8 : 0);
            if (rB > BN - 1) rB = BN - 1;
            int kh = (lane >> 3) & 1;
            int off = rB * 16 + 8 * (kh ^ ((rB >> 2) & 1));
            uint32_t b[2];
            ldsm2(b, baseB + off * 2);
#pragma unroll
            for (int mi = 0; mi < 2; mi++)
                mma16816(acc[mi][12], fa[mi], b[0], b[1]);
        }
    }

    // epilogue: rrelu; write_next -> A fp16 h-region; hout -> fp32 out
    int gq = lane >> 2, tq = lane & 3;
#pragma unroll
    for (int mi = 0; mi < 2; mi++) {
        int row0 = m0 + wm * 32 + mi * 16 + gq;
        int row1 = row0 + 8;
#pragma unroll
        for (int nj = 0; nj < 13; nj++) {
            int col = wn * 104 + nj * 8 + tq * 2;
            if (col >= DD) continue;
            float v0 = acc[mi][nj][0], v1 = acc[mi][nj][1];
            float v2 = acc[mi][nj][2], v3 = acc[mi][nj][3];
            v0 = v0 >= 0.f ? v0 : v0 * SLOPE;
            v1 = v1 >= 0.f ? v1 : v1 * SLOPE;
            v2 = v2 >= 0.f ? v2 : v2 * SLOPE;
            v3 = v3 >= 0.f ? v3 : v3 * SLOPE;
            if (row0 < NN) {
                if (hout) *(float2*)(hout + (size_t)row0 * DD + col) = make_float2(v0, v1);
                if (write_next)
                    *(half2*)(g_Af16 + (size_t)row0 * KP + HOFF + col) = __floats2half2_rn(v0, v1);
            }
            if (row1 < NN) {
                if (hout) *(float2*)(hout + (size_t)row1 * DD + col) = make_float2(v2, v3);
                if (write_next)
                    *(half2*)(g_Af16 + (size_t)row1 * KP + HOFF + col) = __floats2half2_rn(v2, v3);
            }
        }
    }
}

// ---------------- indeg==0 fixup: pre (reads OLD h) + post (scatter) ---------
__global__ void prefix_k(const float* __restrict__ wev) {
    __shared__ float sh[DD];
    int cnt = g_cnt[1];
    for (int j = blockIdx.x; j < cnt; j += gridDim.x) {
        int r = g_list_no[j];
        for (int k = threadIdx.x; k < DD; k += blockDim.x)
            sh[k] = __half2float(g_Af16[(size_t)r * KP + HOFF + k]);
        __syncthreads();
        int c = threadIdx.x;
        if (c < DD) {
            float a = 0.f;
            for (int k = 0; k < DD; k++) a += sh[k] * wev[k * DD + c];
            a = a >= 0.f ? a : a * SLOPE;
            g_fixbuf[(size_t)j * DD + c] = a;
        }
        __syncthreads();
    }
}
__global__ void postfix_k(float* __restrict__ outbuf, int write_next) {
    int cnt = g_cnt[1];
    for (int j = blockIdx.x; j < cnt; j += gridDim.x) {
        int r = g_list_no[j];
        int c = threadIdx.x;
        if (c < DD) {
            float a = g_fixbuf[(size_t)j * DD + c];
            if (write_next) g_Af16[(size_t)r * KP + HOFF + c] = __float2half_rn(a);
            else            outbuf[(size_t)r * DD + c] = a;
        }
    }
}
__global__ void cleanup_k() {
    if (threadIdx.x < 2) g_cnt[threadIdx.x] = 0;
}

// ---------------- launch -----------------------------------------------------
extern "C" void kernel_launch(void* const* d_in, const int* in_sizes, int n_in,
                              void* d_out, int out_size) {
    const float* init_emb = (const float*)d_in[0];
    const float* rel_emb  = (const float*)d_in[1];
    const float* w_neigh  = (const float*)d_in[2];
    const float* w_loop   = (const float*)d_in[3];
    const float* w_evolve = (const float*)d_in[4];
    const float* norm     = (const float*)d_in[5];
    const int*   src      = (const int*)d_in[6];
    const int*   dst      = (const int*)d_in[7];
    const int*   etype    = (const int*)d_in[8];
    const int*   node_id  = (const int*)d_in[9];
    float* out = (float*)d_out;

    count_k<<<(EE + 255) / 256, 256>>>(dst);                      // 0
    s1_k<<<NB, 256>>>();                                          // 1
    s2_k<<<1, 256>>>();                                           // 2
    s3_k<<<NB, 256>>>();                                          // 3
    setup_k<<<FILL_B + INIT_B + WPREP_B, 256>>>(src, dst, etype,  // 4
                                                init_emb, node_id, w_neigh, w_loop);

    int gtiles = (NN + BM - 1) / BM;
    int agrid = (NN + 1) / 2;

    agg_k<<<agrid, 256>>>(rel_emb, norm, 1);                      // 5  <- profiled
    prefix_k<<<64, 256>>>(w_evolve + 0 * DD * DD);
    gemm_mma<<<gtiles, 256>>>(0, (float*)nullptr, 1);
    postfix_k<<<64, 256>>>((float*)nullptr, 1);

    agg_k<<<agrid, 256>>>(rel_emb, norm, 0);
    prefix_k<<<64, 256>>>(w_evolve + 1 * DD * DD);
    gemm_mma<<<gtiles, 256>>>(1, out, 0);
    postfix_k<<<64, 256>>>(out, 0);
    cleanup_k<<<1, 32>>>();
}

// round 9
// speedup vs baseline: 3.9899x; 1.1298x over previous
#include <cuda_runtime.h>
#include <cuda_fp16.h>
#include <cstdint>

#define NN 50000
#define EE 800000
#define DD 200
#define RR 500
#define KP 400           // fused K: [agg 0..199][h 200..399]
#define HOFF 200
#define BM 128
#define BN 208
#define NT 25            // 25 k-chunks (single fp16 pass)
#define SLOPE 0.22916666666666666f
#define NB 196           // ceil(NN/256)
#define AGG_B 12500      // ceil(NN/4) agg blocks
#define PREF_B 16

// ---------------- scratch (zero-initialized at load; invariants restored) ----
__device__ __align__(16) __half g_Af16[(size_t)NN * KP];   // fp16 A: agg | h
__device__ __align__(16) __half g_B16[2 * BN * KP];        // fp16 weights (fused, transposed)
__device__ __align__(16) __half g_rel16[RR * DD];          // fp16 relation embeddings
__device__ float g_relagg[(size_t)NN * DD];
__device__ float g_fixbuf[(size_t)NN * DD];
__device__ int g_indeg[NN];          // zero at entry (restored by s3_k)
__device__ int g_off[NN + 1];
__device__ int g_cur[NN];
__device__ int g_exc[NN];
__device__ int g_bsum[NB];
__device__ int g_bpre[NB];
__device__ unsigned int g_csr[EE];   // src | (etype<<16)
__device__ int g_list_no[NN];
__device__ int g_cnt[2];             // zeroed by s2_k each call

// ---------------- helpers -----------------------------------------------------
__device__ __forceinline__ uint32_t smem_u32(const void* p) {
    uint32_t a;
    asm("{ .reg .u64 t; cvta.to.shared.u64 t, %1; cvt.u32.u64 %0, t; }" : "=r"(a) : "l"(p));
    return a;
}
__device__ __forceinline__ void cp16(uint32_t d, const void* s) {
    asm volatile("cp.async.cg.shared.global [%0], [%1], 16;" :: "r"(d), "l"(s));
}
#define CP_COMMIT() asm volatile("cp.async.commit_group;")
#define CP_WAIT2()  asm volatile("cp.async.wait_group 2;")
__device__ __forceinline__ void ldsm4(uint32_t* r, uint32_t a) {
    asm volatile("ldmatrix.sync.aligned.m8n8.x4.shared.b16 {%0,%1,%2,%3}, [%4];"
                 : "=r"(r[0]), "=r"(r[1]), "=r"(r[2]), "=r"(r[3]) : "r"(a));
}
__device__ __forceinline__ void ldsm2(uint32_t* r, uint32_t a) {
    asm volatile("ldmatrix.sync.aligned.m8n8.x2.shared.b16 {%0,%1}, [%2];"
                 : "=r"(r[0]), "=r"(r[1]) : "r"(a));
}
__device__ __forceinline__ void mma16816(float* c, const uint32_t* a, uint32_t b0, uint32_t b1) {
    asm volatile(
        "mma.sync.aligned.m16n8k16.row.col.f32.f16.f16.f32 "
        "{%0,%1,%2,%3},{%4,%5,%6,%7},{%8,%9},{%0,%1,%2,%3};"
        : "+f"(c[0]), "+f"(c[1]), "+f"(c[2]), "+f"(c[3])
        : "r"(a[0]), "r"(a[1]), "r"(a[2]), "r"(a[3]), "r"(b0), "r"(b1));
}

// ---------------- setup kernels ----------------------------------------------
__global__ void count_k(const int* __restrict__ dst) {
    int e = blockIdx.x * blockDim.x + threadIdx.x;
    if (e < EE) atomicAdd(&g_indeg[dst[e]], 1);
}
__global__ void s1_k() {
    int b = blockIdx.x, t = threadIdx.x, i = b * 256 + t;
    int v = (i < NN) ? g_indeg[i] : 0;
    int lane = t & 31, w = t >> 5;
    int x = v;
#pragma unroll
    for (int o = 1; o < 32; o <<= 1) {
        int y = __shfl_up_sync(0xffffffffu, x, o);
        if (lane >= o) x += y;
    }
    __shared__ int ws[8];
    if (lane == 31) ws[w] = x;
    __syncthreads();
    if (w == 0) {
        int s = (lane < 8) ? ws[lane] : 0;
#pragma unroll
        for (int o = 1; o < 8; o <<= 1) {
            int y = __shfl_up_sync(0xffffffffu, s, o);
            if (lane >= o) s += y;
        }
        if (lane < 8) ws[lane] = s;
    }
    __syncthreads();
    int incl = x + (w > 0 ? ws[w - 1] : 0);
    if (i < NN) g_exc[i] = incl - v;
    if (t == 255) g_bsum[b] = incl;
}
__global__ void s2_k() {
    int t = threadIdx.x;
    if (t < 2) g_cnt[t] = 0;
    int v = (t < NB) ? g_bsum[t] : 0;
    int lane = t & 31, w = t >> 5;
    int x = v;
#pragma unroll
    for (int o = 1; o < 32; o <<= 1) {
        int y = __shfl_up_sync(0xffffffffu, x, o);
        if (lane >= o) x += y;
    }
    __shared__ int ws[8];
    if (lane == 31) ws[w] = x;
    __syncthreads();
    if (w == 0) {
        int s = (lane < 8) ? ws[lane] : 0;
#pragma unroll
        for (int o = 1; o < 8; o <<= 1) {
            int y = __shfl_up_sync(0xffffffffu, s, o);
            if (lane >= o) s += y;
        }
        if (lane < 8) ws[lane] = s;
    }
    __syncthreads();
    int incl = x + (w > 0 ? ws[w - 1] : 0);
    if (t < NB) g_bpre[t] = incl - v;
    if (t == NB - 1) g_off[NN] = incl;
}
__global__ void s3_k() {
    int b = blockIdx.x, t = threadIdx.x, i = b * 256 + t;
    if (i >= NN) return;
    int o = g_exc[i] + g_bpre[b];
    g_off[i] = o;
    g_cur[i] = o;
    if (g_indeg[i] == 0) {
        int p = atomicAdd(&g_cnt[1], 1);
        g_list_no[p] = i;
    }
    g_indeg[i] = 0;   // restore invariant for next call
}
// fused: fill (CSR) + init (A h-region) + wprep (fp16 weights) + rel fp16
#define FILL_B 3125
#define INIT_B 19532
#define WPREP_B 650
#define RELC_B 196       // 500*200/2 = 50000 half2 / 256
__global__ void setup_k(const int* __restrict__ src, const int* __restrict__ dst,
                        const int* __restrict__ et,
                        const float* __restrict__ emb, const int* __restrict__ node_id,
                        const float* __restrict__ wn, const float* __restrict__ wl,
                        const float* __restrict__ rel) {
    int b = blockIdx.x;
    if (b < FILL_B) {
        int e = b * 256 + threadIdx.x;
        if (e < EE) {
            int p = atomicAdd(&g_cur[dst[e]], 1);
            g_csr[p] = (unsigned int)src[e] | ((unsigned int)et[e] << 16);
        }
    } else if (b < FILL_B + INIT_B) {
        long idx = (long)(b - FILL_B) * 256 + threadIdx.x;
        if (idx >= (long)NN * (DD / 2)) return;
        int i = (int)(idx / (DD / 2));
        int c = (int)(idx - (long)i * (DD / 2)) * 2;
        const float* e = emb + (size_t)node_id[i] * DD + c;
        *(half2*)(g_Af16 + (size_t)i * KP + HOFF + c) = __floats2half2_rn(e[0], e[1]);
    } else if (b < FILL_B + INIT_B + WPREP_B) {
        int idx = (b - FILL_B - INIT_B) * 256 + threadIdx.x;
        if (idx >= 2 * BN * KP) return;
        int l = idx / (BN * KP);
        int rem = idx - l * BN * KP;
        int n = rem / KP;
        int k = rem - n * KP;
        float w = 0.f;
        if (n < DD) {
            if (k < DD) w = wn[(size_t)l * DD * DD + k * DD + n];
            else        w = wl[(size_t)l * DD * DD + (k - DD) * DD + n];
        }
        g_B16[idx] = __float2half_rn(w);
    } else {
        int idx = (b - FILL_B - INIT_B - WPREP_B) * 256 + threadIdx.x;
        if (idx >= RR * DD / 2) return;
        int c = idx * 2;
        *(half2*)(g_rel16 + c) = __floats2half2_rn(rel[c], rel[c + 1]);
    }
}

// ---------------- aggregate (+ fused indeg==0 prefix) ------------------------
// blocks [0, AGG_B): 4 nodes/block, 64 threads/node, 4 cols/thread (8B loads)
// blocks [AGG_B, AGG_B+PREF_B): evolve-path fixup compute into g_fixbuf
__global__ void agg_k(const float* __restrict__ norm, int first,
                      const float* __restrict__ wev) {
    if (blockIdx.x < AGG_B) {
        int sub = threadIdx.x >> 6;         // 0..3
        int t = threadIdx.x & 63;
        int i = blockIdx.x * 4 + sub;
        if (i >= NN || t >= DD / 4) return;
        int c = t * 4;
        int s0 = g_off[i], s1 = g_off[i + 1];
        float a0 = 0.f, a1 = 0.f, a2 = 0.f, a3 = 0.f;
        if (first) {
            float r0 = 0.f, r1 = 0.f, r2 = 0.f, r3 = 0.f;
            for (int p = s0; p < s1; p++) {
                unsigned int pe = g_csr[p];
                int sr = pe & 0xFFFF, e = pe >> 16;
                half2 rr[2], hh[2];
                *(int2*)rr = *(const int2*)(g_rel16 + (size_t)e * DD + c);
                *(int2*)hh = *(const int2*)(g_Af16 + (size_t)sr * KP + HOFF + c);
                float2 ra = __half22float2(rr[0]), rb = __half22float2(rr[1]);
                float2 ha = __half22float2(hh[0]), hb = __half22float2(hh[1]);
                r0 += ra.x; r1 += ra.y; r2 += rb.x; r3 += rb.y;
                a0 += ha.x; a1 += ha.y; a2 += hb.x; a3 += hb.y;
            }
            *(float4*)(g_relagg + (size_t)i * DD + c) = make_float4(r0, r1, r2, r3);
            a0 += r0; a1 += r1; a2 += r2; a3 += r3;
        } else {
            float4 r4 = *(const float4*)(g_relagg + (size_t)i * DD + c);
            a0 = r4.x; a1 = r4.y; a2 = r4.z; a3 = r4.w;
            for (int p = s0; p < s1; p++) {
                int sr = g_csr[p] & 0xFFFF;
                half2 hh[2];
                *(int2*)hh = *(const int2*)(g_Af16 + (size_t)sr * KP + HOFF + c);
                float2 ha = __half22float2(hh[0]), hb = __half22float2(hh[1]);
                a0 += ha.x; a1 += ha.y; a2 += hb.x; a3 += hb.y;
            }
        }
        float nm = norm[i];
        half2 o[2] = {__floats2half2_rn(a0 * nm, a1 * nm), __floats2half2_rn(a2 * nm, a3 * nm)};
        *(int2*)(g_Af16 + (size_t)i * KP + c) = *(int2*)o;
    } else {
        // prefix: compute rrelu(h_old @ Wevolve) for indeg==0 nodes
        __shared__ float sh[DD];
        int cnt = g_cnt[1];
        for (int j = blockIdx.x - AGG_B; j < cnt; j += PREF_B) {
            int r = g_list_no[j];
            for (int k = threadIdx.x; k < DD; k += blockDim.x)
                sh[k] = __half2float(g_Af16[(size_t)r * KP + HOFF + k]);
            __syncthreads();
            int c = threadIdx.x;
            if (c < DD) {
                float a = 0.f;
                for (int k = 0; k < DD; k++) a += sh[k] * wev[k * DD + c];
                a = a >= 0.f ? a : a * SLOPE;
                g_fixbuf[(size_t)j * DD + c] = a;
            }
            __syncthreads();
        }
    }
}

// ---------------- pipelined tensor-core GEMM (fp16 single pass) --------------
__global__ __launch_bounds__(256) void gemm_mma(int layer, float* __restrict__ hout,
                                                int write_next) {
    __shared__ __align__(16) __half sA[4][BM * 16];
    __shared__ __align__(16) __half sB[4][BN * 16];

    int tid = threadIdx.x;
    int lane = tid & 31, wid = tid >> 5;
    int wm = wid & 3, wn = wid >> 2;
    int m0 = blockIdx.x * BM;

    const __half* __restrict__ Bw = g_B16 + (size_t)layer * BN * KP;

    float acc[2][13][4];
#pragma unroll
    for (int i = 0; i < 2; i++)
#pragma unroll
        for (int j = 0; j < 13; j++)
#pragma unroll
            for (int q = 0; q < 4; q++) acc[i][j][q] = 0.f;

    int ar = tid >> 1, ah = tid & 1;
    long arow = m0 + ar; if (arow >= NN) arow = 0;
    size_t a_goff = (size_t)arow * KP + ah * 8;
    uint32_t a_sm = smem_u32(sA) + (uint32_t)(ar * 16 + 8 * (ah ^ ((ar >> 2) & 1))) * 2;

    int br0 = tid >> 1, bh0 = tid & 1;
    size_t b_goff0 = (size_t)br0 * KP + bh0 * 8;
    uint32_t b_sm0 = smem_u32(sB) + (uint32_t)(br0 * 16 + 8 * (bh0 ^ ((br0 >> 2) & 1))) * 2;
    int br1 = 128 + (tid >> 1), bh1 = tid & 1;
    size_t b_goff1 = (size_t)br1 * KP + bh1 * 8;
    uint32_t b_sm1 = smem_u32(sB) + (uint32_t)(br1 * 16 + 8 * (bh1 ^ ((br1 >> 2) & 1))) * 2;
    bool bp1 = tid < 160;

    auto issue = [&](int t) {
        int st = t & 3;
        long ko = (long)t * 16;
        cp16(a_sm + st * (BM * 16 * 2), g_Af16 + a_goff + ko);
        cp16(b_sm0 + st * (BN * 16 * 2), Bw + b_goff0 + ko);
        if (bp1) cp16(b_sm1 + st * (BN * 16 * 2), Bw + b_goff1 + ko);
        CP_COMMIT();
    };

    issue(0); issue(1); issue(2);

#pragma unroll 1
    for (int t = 0; t < NT; t++) {
        CP_WAIT2();
        __syncthreads();
        if (t + 3 < NT) issue(t + 3);

        int st = t & 3;
        uint32_t baseA = smem_u32(sA) + st * (BM * 16 * 2);
        uint32_t baseB = smem_u32(sB) + st * (BN * 16 * 2);
        uint32_t fa[2][4];
#pragma unroll
        for (int mi = 0; mi < 2; mi++) {
            int r = wm * 32 + mi * 16 + (lane & 15);
            int kh = lane >> 4;
            int off = r * 16 + 8 * (kh ^ ((r >> 2) & 1));
            ldsm4(fa[mi], baseA + off * 2);
        }
#pragma unroll
        for (int pj = 0; pj < 6; pj++) {
            int rB = wn * 104 + pj * 16 + (lane & 7) + ((lane & 16) ? 8 : 0);
            int kh = (lane >> 3) & 1;
            int off = rB * 16 + 8 * (kh ^ ((rB >> 2) & 1));
            uint32_t b[4];
            ldsm4(b, baseB + off * 2);
#pragma unroll
            for (int mi = 0; mi < 2; mi++) {
                mma16816(acc[mi][2 * pj], fa[mi], b[0], b[1]);
                mma16816(acc[mi][2 * pj + 1], fa[mi], b[2], b[3]);
            }
        }
        if (wn == 0) {   // tail cols 96..103; for wn==1 it's all padding
            int rB = 96 + (lane & 7) + ((lane & 16) ? 8 : 0);
            int kh = (lane >> 3) & 1;
            int off = rB * 16 + 8 * (kh ^ ((rB >> 2) & 1));
            uint32_t b[2];
            ldsm2(b, baseB + off * 2);
#pragma unroll
            for (int mi = 0; mi < 2; mi++)
                mma16816(acc[mi][12], fa[mi], b[0], b[1]);
        }
    }

    // epilogue: rrelu; write_next -> A fp16 h-region; hout -> fp32 out
    int gq = lane >> 2, tq = lane & 3;
#pragma unroll
    for (int mi = 0; mi < 2; mi++) {
        int row0 = m0 + wm * 32 + mi * 16 + gq;
        int row1 = row0 + 8;
#pragma unroll
        for (int nj = 0; nj < 13; nj++) {
            int col = wn * 104 + nj * 8 + tq * 2;
            if (col >= DD) continue;
            float v0 = acc[mi][nj][0], v1 = acc[mi][nj][1];
            float v2 = acc[mi][nj][2], v3 = acc[mi][nj][3];
            v0 = v0 >= 0.f ? v0 : v0 * SLOPE;
            v1 = v1 >= 0.f ? v1 : v1 * SLOPE;
            v2 = v2 >= 0.f ? v2 : v2 * SLOPE;
            v3 = v3 >= 0.f ? v3 : v3 * SLOPE;
            if (row0 < NN) {
                if (hout) *(float2*)(hout + (size_t)row0 * DD + col) = make_float2(v0, v1);
                if (write_next)
                    *(half2*)(g_Af16 + (size_t)row0 * KP + HOFF + col) = __floats2half2_rn(v0, v1);
            }
            if (row1 < NN) {
                if (hout) *(float2*)(hout + (size_t)row1 * DD + col) = make_float2(v2, v3);
                if (write_next)
                    *(half2*)(g_Af16 + (size_t)row1 * KP + HOFF + col) = __floats2half2_rn(v2, v3);
            }
        }
    }
}

// ---------------- indeg==0 scatter -------------------------------------------
__global__ void postfix_k(float* __restrict__ outbuf, int write_next) {
    int cnt = g_cnt[1];
    for (int j = blockIdx.x; j < cnt; j += gridDim.x) {
        int r = g_list_no[j];
        int c = threadIdx.x;
        if (c < DD) {
            float a = g_fixbuf[(size_t)j * DD + c];
            if (write_next) g_Af16[(size_t)r * KP + HOFF + c] = __float2half_rn(a);
            else            outbuf[(size_t)r * DD + c] = a;
        }
    }
}

// ---------------- launch -----------------------------------------------------
extern "C" void kernel_launch(void* const* d_in, const int* in_sizes, int n_in,
                              void* d_out, int out_size) {
    const float* init_emb = (const float*)d_in[0];
    const float* rel_emb  = (const float*)d_in[1];
    const float* w_neigh  = (const float*)d_in[2];
    const float* w_loop   = (const float*)d_in[3];
    const float* w_evolve = (const float*)d_in[4];
    const float* norm     = (const float*)d_in[5];
    const int*   src      = (const int*)d_in[6];
    const int*   dst      = (const int*)d_in[7];
    const int*   etype    = (const int*)d_in[8];
    const int*   node_id  = (const int*)d_in[9];
    float* out = (float*)d_out;

    count_k<<<(EE + 255) / 256, 256>>>(dst);                        // 0
    s1_k<<<NB, 256>>>();                                            // 1
    s2_k<<<1, 256>>>();                                             // 2
    s3_k<<<NB, 256>>>();                                            // 3
    setup_k<<<FILL_B + INIT_B + WPREP_B + RELC_B, 256>>>(           // 4
        src, dst, etype, init_emb, node_id, w_neigh, w_loop, rel_emb);

    int gtiles = (NN + BM - 1) / BM;

    agg_k<<<AGG_B + PREF_B, 256>>>(norm, 1, w_evolve + 0 * DD * DD); // 5 <- profiled
    gemm_mma<<<gtiles, 256>>>(0, (float*)nullptr, 1);                // 6
    postfix_k<<<PREF_B, 256>>>((float*)nullptr, 1);                  // 7

    agg_k<<<AGG_B + PREF_B, 256>>>(norm, 0, w_evolve + 1 * DD * DD); // 8
    gemm_mma<<<gtiles, 256>>>(1, out, 0);                            // 9
    postfix_k<<<PREF_B, 256>>>(out, 0);                              // 10
}

// round 14
// speedup vs baseline: 4.1777x; 1.0471x over previous
#include <cuda_runtime.h>
#include <cuda_fp16.h>
#include <cstdint>

#define NN 50000
#define EE 800000
#define DD 200
#define RR 500
#define KP 400           // fused K: [agg 0..199][h 200..399]
#define HOFF 200
#define BM 128
#define BN 208
#define NT 25            // 25 k-chunks (single fp16 pass)
#define SLOPE 0.22916666666666666f
#define NB 196           // ceil(NN/256)
#define AGG_B 12500      // ceil(NN/4) agg blocks
#define PREF_B 16

// ---------------- scratch (zero-initialized at load; invariants restored) ----
__device__ __align__(16) __half g_Af16[(size_t)NN * KP];   // fp16 A: agg | h
__device__ __align__(16) __half g_B16[2 * BN * KP];        // fp16 weights (fused, transposed)
__device__ __align__(16) __half g_rel16[RR * DD];          // fp16 relation embeddings
__device__ float g_relagg[(size_t)NN * DD];                // fp32 (feeds both layers)
__device__ float g_fixbuf[(size_t)NN * DD];
__device__ int g_indeg[NN];          // zero at entry (restored by s3_k)
__device__ int g_off[NN + 1];
__device__ int g_cur[NN];
__device__ int g_exc[NN];
__device__ int g_bsum[NB];
__device__ int g_bpre[NB];
__device__ unsigned int g_csr[EE];   // src | (etype<<16)
__device__ int g_list_no[NN];
__device__ int g_cnt[2];             // zeroed by s2_k each call

// ---------------- helpers -----------------------------------------------------
__device__ __forceinline__ uint32_t smem_u32(const void* p) {
    uint32_t a;
    asm("{ .reg .u64 t; cvta.to.shared.u64 t, %1; cvt.u32.u64 %0, t; }" : "=r"(a) : "l"(p));
    return a;
}
__device__ __forceinline__ void cp16(uint32_t d, const void* s) {
    asm volatile("cp.async.cg.shared.global [%0], [%1], 16;" :: "r"(d), "l"(s));
}
#define CP_COMMIT() asm volatile("cp.async.commit_group;")
#define CP_WAIT2()  asm volatile("cp.async.wait_group 2;")
__device__ __forceinline__ void ldsm4(uint32_t* r, uint32_t a) {
    asm volatile("ldmatrix.sync.aligned.m8n8.x4.shared.b16 {%0,%1,%2,%3}, [%4];"
                 : "=r"(r[0]), "=r"(r[1]), "=r"(r[2]), "=r"(r[3]) : "r"(a));
}
__device__ __forceinline__ void ldsm2(uint32_t* r, uint32_t a) {
    asm volatile("ldmatrix.sync.aligned.m8n8.x2.shared.b16 {%0,%1}, [%2];"
                 : "=r"(r[0]), "=r"(r[1]) : "r"(a));
}
__device__ __forceinline__ void mma16816(float* c, const uint32_t* a, uint32_t b0, uint32_t b1) {
    asm volatile(
        "mma.sync.aligned.m16n8k16.row.col.f32.f16.f16.f32 "
        "{%0,%1,%2,%3},{%4,%5,%6,%7},{%8,%9},{%0,%1,%2,%3};"
        : "+f"(c[0]), "+f"(c[1]), "+f"(c[2]), "+f"(c[3])
        : "r"(a[0]), "r"(a[1]), "r"(a[2]), "r"(a[3]), "r"(b0), "r"(b1));
}

// ---------------- setup kernels ----------------------------------------------
__global__ void count_k(const int* __restrict__ dst) {
    int e = blockIdx.x * blockDim.x + threadIdx.x;
    if (e < EE) atomicAdd(&g_indeg[dst[e]], 1);
}
__global__ void s1_k() {
    int b = blockIdx.x, t = threadIdx.x, i = b * 256 + t;
    int v = (i < NN) ? g_indeg[i] : 0;
    int lane = t & 31, w = t >> 5;
    int x = v;
#pragma unroll
    for (int o = 1; o < 32; o <<= 1) {
        int y = __shfl_up_sync(0xffffffffu, x, o);
        if (lane >= o) x += y;
    }
    __shared__ int ws[8];
    if (lane == 31) ws[w] = x;
    __syncthreads();
    if (w == 0) {
        int s = (lane < 8) ? ws[lane] : 0;
#pragma unroll
        for (int o = 1; o < 8; o <<= 1) {
            int y = __shfl_up_sync(0xffffffffu, s, o);
            if (lane >= o) s += y;
        }
        if (lane < 8) ws[lane] = s;
    }
    __syncthreads();
    int incl = x + (w > 0 ? ws[w - 1] : 0);
    if (i < NN) g_exc[i] = incl - v;
    if (t == 255) g_bsum[b] = incl;
}
__global__ void s2_k() {
    int t = threadIdx.x;
    if (t < 2) g_cnt[t] = 0;
    int v = (t < NB) ? g_bsum[t] : 0;
    int lane = t & 31, w = t >> 5;
    int x = v;
#pragma unroll
    for (int o = 1; o < 32; o <<= 1) {
        int y = __shfl_up_sync(0xffffffffu, x, o);
        if (lane >= o) x += y;
    }
    __shared__ int ws[8];
    if (lane == 31) ws[w] = x;
    __syncthreads();
    if (w == 0) {
        int s = (lane < 8) ? ws[lane] : 0;
#pragma unroll
        for (int o = 1; o < 8; o <<= 1) {
            int y = __shfl_up_sync(0xffffffffu, s, o);
            if (lane >= o) s += y;
        }
        if (lane < 8) ws[lane] = s;
    }
    __syncthreads();
    int incl = x + (w > 0 ? ws[w - 1] : 0);
    if (t < NB) g_bpre[t] = incl - v;
    if (t == NB - 1) g_off[NN] = incl;
}
__global__ void s3_k() {
    int b = blockIdx.x, t = threadIdx.x, i = b * 256 + t;
    if (i >= NN) return;
    int o = g_exc[i] + g_bpre[b];
    g_off[i] = o;
    g_cur[i] = o;
    if (g_indeg[i] == 0) {
        int p = atomicAdd(&g_cnt[1], 1);
        g_list_no[p] = i;
    }
    g_indeg[i] = 0;   // restore invariant for next call
}
// fused: fill (CSR) + init (A h-region) + wprep (fp16 weights) + rel fp16
#define FILL_B 3125
#define INIT_B 19532
#define WPREP_B 650
#define RELC_B 196
__global__ void setup_k(const int* __restrict__ src, const int* __restrict__ dst,
                        const int* __restrict__ et,
                        const float* __restrict__ emb, const int* __restrict__ node_id,
                        const float* __restrict__ wn, const float* __restrict__ wl,
                        const float* __restrict__ rel) {
    int b = blockIdx.x;
    if (b < FILL_B) {
        int e = b * 256 + threadIdx.x;
        if (e < EE) {
            int p = atomicAdd(&g_cur[dst[e]], 1);
            g_csr[p] = (unsigned int)src[e] | ((unsigned int)et[e] << 16);
        }
    } else if (b < FILL_B + INIT_B) {
        long idx = (long)(b - FILL_B) * 256 + threadIdx.x;
        if (idx >= (long)NN * (DD / 2)) return;
        int i = (int)(idx / (DD / 2));
        int c = (int)(idx - (long)i * (DD / 2)) * 2;
        const float* e = emb + (size_t)node_id[i] * DD + c;
        *(half2*)(g_Af16 + (size_t)i * KP + HOFF + c) = __floats2half2_rn(e[0], e[1]);
    } else if (b < FILL_B + INIT_B + WPREP_B) {
        int idx = (b - FILL_B - INIT_B) * 256 + threadIdx.x;
        if (idx >= 2 * BN * KP) return;
        int l = idx / (BN * KP);
        int rem = idx - l * BN * KP;
        int n = rem / KP;
        int k = rem - n * KP;
        float w = 0.f;
        if (n < DD) {
            if (k < DD) w = wn[(size_t)l * DD * DD + k * DD + n];
            else        w = wl[(size_t)l * DD * DD + (k - DD) * DD + n];
        }
        g_B16[idx] = __float2half_rn(w);
    } else {
        int idx = (b - FILL_B - INIT_B - WPREP_B) * 256 + threadIdx.x;
        if (idx >= RR * DD / 2) return;
        int c = idx * 2;
        *(half2*)(g_rel16 + c) = __floats2half2_rn(rel[c], rel[c + 1]);
    }
}

// ---------------- aggregate (+ fused indeg==0 prefix) ------------------------
__global__ void agg_k(const float* __restrict__ norm, int first,
                      const float* __restrict__ wev) {
    if (blockIdx.x < AGG_B) {
        int sub = threadIdx.x >> 6;         // 0..3
        int t = threadIdx.x & 63;
        int i = blockIdx.x * 4 + sub;
        if (i >= NN || t >= DD / 4) return;
        int c = t * 4;
        int s0 = g_off[i], s1 = g_off[i + 1];
        float a0 = 0.f, a1 = 0.f, a2 = 0.f, a3 = 0.f;
        if (first) {
            float r0 = 0.f, r1 = 0.f, r2 = 0.f, r3 = 0.f;
            for (int p = s0; p < s1; p++) {
                unsigned int pe = g_csr[p];
                int sr = pe & 0xFFFF, e = pe >> 16;
                half2 rr[2], hh[2];
                *(int2*)rr = *(const int2*)(g_rel16 + (size_t)e * DD + c);
                *(int2*)hh = *(const int2*)(g_Af16 + (size_t)sr * KP + HOFF + c);
                float2 ra = __half22float2(rr[0]), rb = __half22float2(rr[1]);
                float2 ha = __half22float2(hh[0]), hb = __half22float2(hh[1]);
                r0 += ra.x; r1 += ra.y; r2 += rb.x; r3 += rb.y;
                a0 += ha.x; a1 += ha.y; a2 += hb.x; a3 += hb.y;
            }
            *(float4*)(g_relagg + (size_t)i * DD + c) = make_float4(r0, r1, r2, r3);
            a0 += r0; a1 += r1; a2 += r2; a3 += r3;
        } else {
            float4 r4 = *(const float4*)(g_relagg + (size_t)i * DD + c);
            a0 = r4.x; a1 = r4.y; a2 = r4.z; a3 = r4.w;
            for (int p = s0; p < s1; p++) {
                int sr = g_csr[p] & 0xFFFF;
                half2 hh[2];
                *(int2*)hh = *(const int2*)(g_Af16 + (size_t)sr * KP + HOFF + c);
                float2 ha = __half22float2(hh[0]), hb = __half22float2(hh[1]);
                a0 += ha.x; a1 += ha.y; a2 += hb.x; a3 += hb.y;
            }
        }
        float nm = norm[i];
        half2 o[2] = {__floats2half2_rn(a0 * nm, a1 * nm), __floats2half2_rn(a2 * nm, a3 * nm)};
        *(int2*)(g_Af16 + (size_t)i * KP + c) = *(int2*)o;
    } else {
        // prefix: compute rrelu(h_old @ Wevolve) for indeg==0 nodes
        __shared__ float sh[DD];
        int cnt = g_cnt[1];
        for (int j = blockIdx.x - AGG_B; j < cnt; j += PREF_B) {
            int r = g_list_no[j];
            for (int k = threadIdx.x; k < DD; k += blockDim.x)
                sh[k] = __half2float(g_Af16[(size_t)r * KP + HOFF + k]);
            __syncthreads();
            int c = threadIdx.x;
            if (c < DD) {
                float a = 0.f;
                for (int k = 0; k < DD; k++) a += sh[k] * wev[k * DD + c];
                a = a >= 0.f ? a : a * SLOPE;
                g_fixbuf[(size_t)j * DD + c] = a;
            }
            __syncthreads();
        }
    }
}

// ---------------- pipelined tensor-core GEMM (fp16 single pass) --------------
// Single CTA owns the full n-range per m-tile (write-after-own-read safe).
// Experiment this round: min-blocks=2 -> 2 CTAs/SM (reg cap 128).
__global__ __launch_bounds__(256, 2) void gemm_mma(int layer, float* __restrict__ hout,
                                                   int write_next) {
    __shared__ __align__(16) __half sA[4][BM * 16];
    __shared__ __align__(16) __half sB[4][BN * 16];

    int tid = threadIdx.x;
    int lane = tid & 31, wid = tid >> 5;
    int wm = wid & 3, wn = wid >> 2;
    int m0 = blockIdx.x * BM;

    const __half* __restrict__ Bw = g_B16 + (size_t)layer * BN * KP;

    float acc[2][13][4];
#pragma unroll
    for (int i = 0; i < 2; i++)
#pragma unroll
        for (int j = 0; j < 13; j++)
#pragma unroll
            for (int q = 0; q < 4; q++) acc[i][j][q] = 0.f;

    int ar = tid >> 1, ah = tid & 1;
    long arow = m0 + ar; if (arow >= NN) arow = 0;
    size_t a_goff = (size_t)arow * KP + ah * 8;
    uint32_t a_sm = smem_u32(sA) + (uint32_t)(ar * 16 + 8 * (ah ^ ((ar >> 2) & 1))) * 2;

    int br0 = tid >> 1, bh0 = tid & 1;
    size_t b_goff0 = (size_t)br0 * KP + bh0 * 8;
    uint32_t b_sm0 = smem_u32(sB) + (uint32_t)(br0 * 16 + 8 * (bh0 ^ ((br0 >> 2) & 1))) * 2;
    int br1 = 128 + (tid >> 1), bh1 = tid & 1;
    size_t b_goff1 = (size_t)br1 * KP + bh1 * 8;
    uint32_t b_sm1 = smem_u32(sB) + (uint32_t)(br1 * 16 + 8 * (bh1 ^ ((br1 >> 2) & 1))) * 2;
    bool bp1 = tid < 160;

    auto issue = [&](int t) {
        int st = t & 3;
        long ko = (long)t * 16;
        cp16(a_sm + st * (BM * 16 * 2), g_Af16 + a_goff + ko);
        cp16(b_sm0 + st * (BN * 16 * 2), Bw + b_goff0 + ko);
        if (bp1) cp16(b_sm1 + st * (BN * 16 * 2), Bw + b_goff1 + ko);
        CP_COMMIT();
    };

    issue(0); issue(1); issue(2);

#pragma unroll 1
    for (int t = 0; t < NT; t++) {
        CP_WAIT2();
        __syncthreads();
        if (t + 3 < NT) issue(t + 3);

        int st = t & 3;
        uint32_t baseA = smem_u32(sA) + st * (BM * 16 * 2);
        uint32_t baseB = smem_u32(sB) + st * (BN * 16 * 2);
        uint32_t fa[2][4];
#pragma unroll
        for (int mi = 0; mi < 2; mi++) {
            int r = wm * 32 + mi * 16 + (lane & 15);
            int kh = lane >> 4;
            int off = r * 16 + 8 * (kh ^ ((r >> 2) & 1));
            ldsm4(fa[mi], baseA + off * 2);
        }
#pragma unroll
        for (int pj = 0; pj < 6; pj++) {
            int rB = wn * 104 + pj * 16 + (lane & 7) + ((lane & 16) ? 8 : 0);
            int kh = (lane >> 3) & 1;
            int off = rB * 16 + 8 * (kh ^ ((rB >> 2) & 1));
            uint32_t b[4];
            ldsm4(b, baseB + off * 2);
#pragma unroll
            for (int mi = 0; mi < 2; mi++) {
                mma16816(acc[mi][2 * pj], fa[mi], b[0], b[1]);
                mma16816(acc[mi][2 * pj + 1], fa[mi], b[2], b[3]);
            }
        }
        if (wn == 0) {   // tail cols 96..103; for wn==1 it's all padding
            int rB = 96 + (lane & 7) + ((lane & 16) ? 8 : 0);
            int kh = (lane >> 3) & 1;
            int off = rB * 16 + 8 * (kh ^ ((rB >> 2) & 1));
            uint32_t b[2];
            ldsm2(b, baseB + off * 2);
#pragma unroll
            for (int mi = 0; mi < 2; mi++)
                mma16816(acc[mi][12], fa[mi], b[0], b[1]);
        }
    }

    // epilogue: rrelu; write_next -> A fp16 h-region; hout -> fp32 out
    int gq = lane >> 2, tq = lane & 3;
#pragma unroll
    for (int mi = 0; mi < 2; mi++) {
        int row0 = m0 + wm * 32 + mi * 16 + gq;
        int row1 = row0 + 8;
#pragma unroll
        for (int nj = 0; nj < 13; nj++) {
            int col = wn * 104 + nj * 8 + tq * 2;
            if (col >= DD) continue;
            float v0 = acc[mi][nj][0], v1 = acc[mi][nj][1];
            float v2 = acc[mi][nj][2], v3 = acc[mi][nj][3];
            v0 = v0 >= 0.f ? v0 : v0 * SLOPE;
            v1 = v1 >= 0.f ? v1 : v1 * SLOPE;
            v2 = v2 >= 0.f ? v2 : v2 * SLOPE;
            v3 = v3 >= 0.f ? v3 : v3 * SLOPE;
            if (row0 < NN) {
                if (hout) *(float2*)(hout + (size_t)row0 * DD + col) = make_float2(v0, v1);
                if (write_next)
                    *(half2*)(g_Af16 + (size_t)row0 * KP + HOFF + col) = __floats2half2_rn(v0, v1);
            }
            if (row1 < NN) {
                if (hout) *(float2*)(hout + (size_t)row1 * DD + col) = make_float2(v2, v3);
                if (write_next)
                    *(half2*)(g_Af16 + (size_t)row1 * KP + HOFF + col) = __floats2half2_rn(v2, v3);
            }
        }
    }
}

// ---------------- indeg==0 scatter -------------------------------------------
__global__ void postfix_k(float* __restrict__ outbuf, int write_next) {
    int cnt = g_cnt[1];
    for (int j = blockIdx.x; j < cnt; j += gridDim.x) {
        int r = g_list_no[j];
        int c = threadIdx.x;
        if (c < DD) {
            float a = g_fixbuf[(size_t)j * DD + c];
            if (write_next) g_Af16[(size_t)r * KP + HOFF + c] = __float2half_rn(a);
            else            outbuf[(size_t)r * DD + c] = a;
        }
    }
}

// ---------------- launch -----------------------------------------------------
extern "C" void kernel_launch(void* const* d_in, const int* in_sizes, int n_in,
                              void* d_out, int out_size) {
    const float* init_emb = (const float*)d_in[0];
    const float* rel_emb  = (const float*)d_in[1];
    const float* w_neigh  = (const float*)d_in[2];
    const float* w_loop   = (const float*)d_in[3];
    const float* w_evolve = (const float*)d_in[4];
    const float* norm     = (const float*)d_in[5];
    const int*   src      = (const int*)d_in[6];
    const int*   dst      = (const int*)d_in[7];
    const int*   etype    = (const int*)d_in[8];
    const int*   node_id  = (const int*)d_in[9];
    float* out = (float*)d_out;

    count_k<<<(EE + 255) / 256, 256>>>(dst);                        // 0
    s1_k<<<NB, 256>>>();                                            // 1
    s2_k<<<1, 256>>>();                                             // 2
    s3_k<<<NB, 256>>>();                                            // 3
    setup_k<<<FILL_B + INIT_B + WPREP_B + RELC_B, 256>>>(           // 4
        src, dst, etype, init_emb, node_id, w_neigh, w_loop, rel_emb);

    int gtiles = (NN + BM - 1) / BM;

    agg_k<<<AGG_B + PREF_B, 256>>>(norm, 1, w_evolve + 0 * DD * DD); // 5 <- profiled
    gemm_mma<<<gtiles, 256>>>(0, (float*)nullptr, 1);                // 6
    postfix_k<<<PREF_B, 256>>>((float*)nullptr, 1);                  // 7

    agg_k<<<AGG_B + PREF_B, 256>>>(norm, 0, w_evolve + 1 * DD * DD); // 8
    gemm_mma<<<gtiles, 256>>>(1, out, 0);                            // 9
    postfix_k<<<PREF_B, 256>>>(out, 0);                              // 10
}